// round 4
// baseline (speedup 1.0000x reference)
#include <cuda_runtime.h>
#include <math.h>

#define B_ 2
#define S_ 1024
#define D_ 768
#define H_ 12
#define E_ 8
#define DH_ 64
#define DFF_ 2048
#define NTOK (B_*S_)
#define CAP_ 320
#define NOUT (NTOK*D_)

#define TM 128
#define TN 128
#define TK 8

// ---------------- scratch (device globals; no allocation allowed) -------------
__device__ float g_xln [NTOK*D_];
__device__ float g_q   [NTOK*D_];
__device__ float g_k   [NTOK*D_];
__device__ float g_vsel[NTOK*D_];
__device__ float g_attn[NTOK*D_];
__device__ float g_x1  [NTOK*D_];
__device__ float g_xln2[NTOK*D_];
__device__ int   g_eidx[NTOK*H_];
__device__ int   g_hard[H_*E_];
__device__ float g_m[B_*H_*S_];
__device__ float g_l[B_*H_*S_];
__device__ int   g_tk_idx[NTOK*2];
__device__ float g_tk_prob[NTOK*2];
__device__ int   g_token_slot[NTOK*2];
__device__ int   g_slot_token[E_*CAP_];   // zero-init; entries >= count never written
__device__ float g_slot_w[E_*CAP_];
__device__ int   g_ecount[E_];
__device__ float g_hbuf[E_*CAP_*DFF_];    // zero-init; rows >= count stay zero
__device__ float g_sout[E_*CAP_*D_];

// ---------------- LayerNorm ---------------------------------------------------
__global__ void ln_kernel(const float* __restrict__ x, const float* __restrict__ g,
                          const float* __restrict__ b, float* __restrict__ out) {
    int row = blockIdx.x, tid = threadIdx.x;
    const float* xr = x + (size_t)row * D_;
    float s = 0.f, s2 = 0.f;
    for (int d = tid; d < D_; d += 256) { float v = xr[d]; s += v; s2 += v * v; }
    for (int o = 16; o > 0; o >>= 1) {
        s  += __shfl_down_sync(0xffffffffu, s,  o);
        s2 += __shfl_down_sync(0xffffffffu, s2, o);
    }
    __shared__ float sh[8], sh2[8];
    int w = tid >> 5, lane = tid & 31;
    if (lane == 0) { sh[w] = s; sh2[w] = s2; }
    __syncthreads();
    __shared__ float smean, sinv;
    if (tid == 0) {
        float a = 0.f, a2 = 0.f;
        for (int i = 0; i < 8; i++) { a += sh[i]; a2 += sh2[i]; }
        float mean = a / D_;
        float var  = a2 / D_ - mean * mean;
        smean = mean; sinv = rsqrtf(var + 1e-5f);
    }
    __syncthreads();
    float mean = smean, inv = sinv;
    for (int d = tid; d < D_; d += 256)
        out[(size_t)row * D_ + d] = (xr[d] - mean) * inv * g[d] + b[d];
}

// ---------------- big tiled SGEMM: 128x128 tile, 8x8/thread, double buffered --
// MODE 0: Q/K projection.  z=0 -> B=P0(Wq), C=g_q ; z=1 -> B=P1(Wk), C=g_k.
//         A = g_xln, M=NTOK, N=D_, K=D_.
// MODE 1: FFN GEMM1 (gathered A rows, ReLU). z=e. B=P0=W1. C=g_hbuf. N=DFF_, K=D_.
// MODE 2: FFN GEMM2 (scaled by slot weight). z=e. B=P0=W2. C=g_sout. N=D_, K=DFF_.
template<int MODE>
__global__ __launch_bounds__(256)
void gemm_big(const float* __restrict__ P0, const float* __restrict__ P1) {
    __shared__ float As[2][TK][132];
    __shared__ float Bs[2][TK][128];

    const int tid = threadIdx.x;
    const int e   = blockIdx.z;
    const int m0  = blockIdx.y * TM;
    const int n0  = blockIdx.x * TN;

    int N, K, count;
    const float* Bm;
    float* C;
    const float* Abase;
    if (MODE == 0) {
        N = D_; K = D_; count = NTOK;
        Bm = (e == 0) ? P0 : P1;
        C  = (e == 0) ? g_q : g_k;
        Abase = g_xln;
    } else if (MODE == 1) {
        N = DFF_; K = D_; count = g_ecount[e];
        if (m0 >= count) return;
        Bm = P0 + (size_t)e * D_ * DFF_;
        C  = g_hbuf + (size_t)e * CAP_ * DFF_;
        Abase = g_xln2;
    } else {
        N = D_; K = DFF_; count = g_ecount[e];
        if (m0 >= count) return;
        Bm = P0 + (size_t)e * DFF_ * D_;
        C  = g_sout + (size_t)e * CAP_ * D_;
        Abase = g_hbuf + (size_t)e * CAP_ * DFF_;
    }

    // --- global->smem staging indices ---
    const int ar = tid >> 1;            // A tile row 0..127
    const int ak = (tid & 1) * 4;       // A tile col group {0,4}
    const int brow = tid >> 5;          // B tile row 0..7
    const int bcol = (tid & 31) * 4;    // B tile col group

    const float* Aptr;
    {
        int arow = m0 + ar;
        int r = (arow < count) ? arow : (count > 0 ? count - 1 : 0);
        if (MODE == 1)
            Aptr = Abase + (size_t)g_slot_token[e * CAP_ + r] * D_ + ak;
        else
            Aptr = Abase + (size_t)r * K + ak;
    }
    const float* Bptr = Bm + (size_t)brow * N + n0 + bcol;

    const int tx4 = (tid & 15) * 4;
    const int ty4 = (tid >> 4) * 4;

    float acc[8][8];
#pragma unroll
    for (int i = 0; i < 8; i++)
#pragma unroll
        for (int j = 0; j < 8; j++) acc[i][j] = 0.f;

    const int nk = K / TK;

    // preload tile 0
    {
        float4 a = *(const float4*)(Aptr);
        float4 b = *(const float4*)(Bptr);
        As[0][ak + 0][ar] = a.x; As[0][ak + 1][ar] = a.y;
        As[0][ak + 2][ar] = a.z; As[0][ak + 3][ar] = a.w;
        *(float4*)&Bs[0][brow][bcol] = b;
    }
    __syncthreads();

    int buf = 0;
    for (int kb = 0; kb < nk; kb++) {
        float4 an, bn;
        if (kb + 1 < nk) {
            an = *(const float4*)(Aptr + (size_t)(kb + 1) * TK);
            bn = *(const float4*)(Bptr + (size_t)(kb + 1) * TK * N);
        }
        float (*Asb)[132] = As[buf];
        float (*Bsb)[128] = Bs[buf];
#pragma unroll
        for (int k = 0; k < TK; k++) {
            float va[8], vb[8];
            float4 t;
            t = *(const float4*)&Asb[k][ty4];      va[0]=t.x; va[1]=t.y; va[2]=t.z; va[3]=t.w;
            t = *(const float4*)&Asb[k][ty4 + 64]; va[4]=t.x; va[5]=t.y; va[6]=t.z; va[7]=t.w;
            t = *(const float4*)&Bsb[k][tx4];      vb[0]=t.x; vb[1]=t.y; vb[2]=t.z; vb[3]=t.w;
            t = *(const float4*)&Bsb[k][tx4 + 64]; vb[4]=t.x; vb[5]=t.y; vb[6]=t.z; vb[7]=t.w;
#pragma unroll
            for (int i = 0; i < 8; i++)
#pragma unroll
                for (int j = 0; j < 8; j++) acc[i][j] += va[i] * vb[j];
        }
        if (kb + 1 < nk) {
            float (*Asn)[132] = As[buf ^ 1];
            float (*Bsn)[128] = Bs[buf ^ 1];
            Asn[ak + 0][ar] = an.x; Asn[ak + 1][ar] = an.y;
            Asn[ak + 2][ar] = an.z; Asn[ak + 3][ar] = an.w;
            *(float4*)&Bsn[brow][bcol] = bn;
        }
        __syncthreads();
        buf ^= 1;
    }

    // --- store ---
#pragma unroll
    for (int im = 0; im < 8; im++) {
        int m = m0 + ((im < 4) ? (ty4 + im) : (64 + ty4 + im - 4));
        if (MODE != 0 && m >= count) continue;
        float wgt = 1.f;
        if (MODE == 2) wgt = g_slot_w[e * CAP_ + m];
        float4 o0, o1;
        if (MODE == 1) {
            o0 = make_float4(fmaxf(acc[im][0],0.f), fmaxf(acc[im][1],0.f),
                             fmaxf(acc[im][2],0.f), fmaxf(acc[im][3],0.f));
            o1 = make_float4(fmaxf(acc[im][4],0.f), fmaxf(acc[im][5],0.f),
                             fmaxf(acc[im][6],0.f), fmaxf(acc[im][7],0.f));
        } else if (MODE == 2) {
            o0 = make_float4(wgt*acc[im][0], wgt*acc[im][1], wgt*acc[im][2], wgt*acc[im][3]);
            o1 = make_float4(wgt*acc[im][4], wgt*acc[im][5], wgt*acc[im][6], wgt*acc[im][7]);
        } else {
            o0 = make_float4(acc[im][0], acc[im][1], acc[im][2], acc[im][3]);
            o1 = make_float4(acc[im][4], acc[im][5], acc[im][6], acc[im][7]);
        }
        *(float4*)(C + (size_t)m * N + n0 + tx4)      = o0;
        *(float4*)(C + (size_t)m * N + n0 + tx4 + 64) = o1;
    }
}

// ---------------- attention router: argmax expert per (token, head) -----------
__global__ void zero_hard() { int i = threadIdx.x; if (i < H_ * E_) g_hard[i] = 0; }

__global__ void router_kernel(const float* __restrict__ Wr) {
    int row = blockIdx.x, tid = threadIdx.x; // 128
    __shared__ float xr[D_];
    __shared__ float lg[H_ * E_];
    for (int d = tid; d < D_; d += 128) xr[d] = g_xln[(size_t)row * D_ + d];
    __syncthreads();
    if (tid < H_ * E_) {
        float acc = 0.f;
        for (int d = 0; d < D_; d++) acc += xr[d] * Wr[(size_t)d * (H_ * E_) + tid];
        lg[tid] = acc;
    }
    __syncthreads();
    if (tid < H_) {
        int h = tid;
        float best = lg[h * E_]; int bi = 0;
        for (int e = 1; e < E_; e++) { float v = lg[h * E_ + e]; if (v > best) { best = v; bi = e; } }
        g_eidx[row * H_ + h] = bi;
        atomicAdd(&g_hard[h * E_ + bi], 1);
    }
}

// ---------------- per (token, head) expert matvecs ----------------------------
__global__ void vsel_kernel(const float* __restrict__ Wv) {
    int row = blockIdx.x, tid = threadIdx.x; // 384 = 12 warps
    int h = tid >> 5, lane = tid & 31;
    int e = g_eidx[row * H_ + h];
    const float* wv = Wv + (size_t)(h * E_ + e) * DH_ * DH_;
    const float* xh = g_xln + (size_t)row * D_ + h * DH_;
    float a0 = 0.f, a1 = 0.f;
    for (int d = 0; d < DH_; d++) {
        float xv = xh[d];
        a0 += xv * wv[d * DH_ + lane];
        a1 += xv * wv[d * DH_ + lane + 32];
    }
    g_vsel[(size_t)row * D_ + h * DH_ + lane]      = a0;
    g_vsel[(size_t)row * D_ + h * DH_ + lane + 32] = a1;
}

__global__ void osel_kernel(const float* __restrict__ Wo, const float* __restrict__ x) {
    int row = blockIdx.x, tid = threadIdx.x; // 384
    int h = tid >> 5, lane = tid & 31;
    int e = g_eidx[row * H_ + h];
    const float* wo = Wo + (size_t)(h * E_ + e) * DH_ * DH_;
    const float* af = g_attn + (size_t)row * D_ + h * DH_;
    float a0 = 0.f, a1 = 0.f;
    for (int f = 0; f < DH_; f++) {
        float av = af[f];
        a0 += av * wo[f * DH_ + lane];
        a1 += av * wo[f * DH_ + lane + 32];
    }
    size_t o0 = (size_t)row * D_ + h * DH_ + lane;
    g_x1[o0]      = x[o0]      + a0;
    g_x1[o0 + 32] = x[o0 + 32] + a1;
}

// ---------------- attention pass 1: exact softmax row stats (m_s, l_s) --------
__global__ void attn_pass1() {
    int s0 = blockIdx.x * 64;
    int h = blockIdx.y, b = blockIdx.z;
    int tid = threadIdx.x;
    __shared__ float Qs[64][65];
    __shared__ float Ks[64][65];
    __shared__ float red[64][16];
    __shared__ float sm[64], sl[64], sal[64];
    const float* qb = g_q + (size_t)b * S_ * D_ + h * DH_;
    const float* kb = g_k + (size_t)b * S_ * D_ + h * DH_;
#pragma unroll
    for (int i = 0; i < 16; i++) {
        int idx = tid + i * 256; int r = idx >> 6, d = idx & 63;
        Qs[r][d] = qb[(size_t)(s0 + r) * D_ + d];
    }
    if (tid < 64) { sm[tid] = -INFINITY; sl[tid] = 0.f; }
    __syncthreads();
    int rm = tid >> 4, cn = tid & 15;
    for (int t0 = 0; t0 <= s0; t0 += 64) {
#pragma unroll
        for (int i = 0; i < 16; i++) {
            int idx = tid + i * 256; int r = idx >> 6, d = idx & 63;
            Ks[r][d] = kb[(size_t)(t0 + r) * D_ + d];
        }
        __syncthreads();
        float sv[4][4] = {};
        for (int d = 0; d < 64; d++) {
            float qa[4], ka[4];
#pragma unroll
            for (int i = 0; i < 4; i++) qa[i] = Qs[rm * 4 + i][d];
#pragma unroll
            for (int j = 0; j < 4; j++) ka[j] = Ks[cn * 4 + j][d];
#pragma unroll
            for (int i = 0; i < 4; i++)
#pragma unroll
                for (int j = 0; j < 4; j++) sv[i][j] += qa[i] * ka[j];
        }
#pragma unroll
        for (int i = 0; i < 4; i++) {
            int gs = s0 + rm * 4 + i;
            float mx = -INFINITY;
#pragma unroll
            for (int j = 0; j < 4; j++) {
                int gt = t0 + cn * 4 + j;
                sv[i][j] = sv[i][j] * 0.125f + ((gt <= gs) ? 0.f : -1e9f);
                mx = fmaxf(mx, sv[i][j]);
            }
            red[rm * 4 + i][cn] = mx;
        }
        __syncthreads();
        if (tid < 64) {
            float mt = red[tid][0];
            for (int c = 1; c < 16; c++) mt = fmaxf(mt, red[tid][c]);
            float mo = sm[tid], mn = fmaxf(mo, mt);
            sm[tid] = mn; sal[tid] = expf(mo - mn);
        }
        __syncthreads();
#pragma unroll
        for (int i = 0; i < 4; i++) {
            float m = sm[rm * 4 + i];
            float s = 0.f;
#pragma unroll
            for (int j = 0; j < 4; j++) s += expf(sv[i][j] - m);
            red[rm * 4 + i][cn] = s;
        }
        __syncthreads();
        if (tid < 64) {
            float s = 0.f;
            for (int c = 0; c < 16; c++) s += red[tid][c];
            sl[tid] = sl[tid] * sal[tid] + s;
        }
        __syncthreads();
    }
    if (tid < 64) {
        int o = (b * H_ + h) * S_ + s0 + tid;
        g_m[o] = sm[tid]; g_l[o] = sl[tid];
    }
}

// ---------------- attention pass 2: out[t] = sum_{s>=t} P[s,t] * v[s] ---------
__global__ void attn_pass2() {
    extern __shared__ float dsm[];
    float (*Ks)[65] = (float(*)[65])dsm;
    float (*Qs)[65] = (float(*)[65])(dsm + 64 * 65);
    float (*Vs)[65] = (float(*)[65])(dsm + 2 * 64 * 65);
    float (*Ps)[65] = (float(*)[65])(dsm + 3 * 64 * 65);
    float* srm  = dsm + 4 * 64 * 65;
    float* sinv = srm + 64;
    int t0 = blockIdx.x * 64;
    int h = blockIdx.y, b = blockIdx.z;
    int tid = threadIdx.x;
    const float* qb = g_q    + (size_t)b * S_ * D_ + h * DH_;
    const float* kb = g_k    + (size_t)b * S_ * D_ + h * DH_;
    const float* vb = g_vsel + (size_t)b * S_ * D_ + h * DH_;
#pragma unroll
    for (int i = 0; i < 16; i++) {
        int idx = tid + i * 256; int r = idx >> 6, d = idx & 63;
        Ks[r][d] = kb[(size_t)(t0 + r) * D_ + d];
    }
    float O[4][4] = {};
    int sr = tid >> 4, tn = tid & 15;
    for (int st0 = t0; st0 < S_; st0 += 64) {
#pragma unroll
        for (int i = 0; i < 16; i++) {
            int idx = tid + i * 256; int r = idx >> 6, d = idx & 63;
            Qs[r][d] = qb[(size_t)(st0 + r) * D_ + d];
            Vs[r][d] = vb[(size_t)(st0 + r) * D_ + d];
        }
        if (tid < 64) {
            int o = (b * H_ + h) * S_ + st0 + tid;
            srm[tid] = g_m[o]; sinv[tid] = 1.f / g_l[o];
        }
        __syncthreads();
        float sv[4][4] = {};
        for (int d = 0; d < 64; d++) {
            float qa[4], ka[4];
#pragma unroll
            for (int i = 0; i < 4; i++) qa[i] = Qs[sr * 4 + i][d];
#pragma unroll
            for (int j = 0; j < 4; j++) ka[j] = Ks[tn * 4 + j][d];
#pragma unroll
            for (int i = 0; i < 4; i++)
#pragma unroll
                for (int j = 0; j < 4; j++) sv[i][j] += qa[i] * ka[j];
        }
#pragma unroll
        for (int i = 0; i < 4; i++) {
            int gs = st0 + sr * 4 + i;
            float m = srm[sr * 4 + i], iv = sinv[sr * 4 + i];
#pragma unroll
            for (int j = 0; j < 4; j++) {
                int gt = t0 + tn * 4 + j;
                float p = (gt <= gs) ? expf(sv[i][j] * 0.125f - m) * iv : 0.f;
                Ps[sr * 4 + i][tn * 4 + j] = p;
            }
        }
        __syncthreads();
        for (int s = 0; s < 64; s++) {
            float pv[4], vv[4];
#pragma unroll
            for (int i = 0; i < 4; i++) pv[i] = Ps[s][sr * 4 + i];
#pragma unroll
            for (int j = 0; j < 4; j++) vv[j] = Vs[s][tn * 4 + j];
#pragma unroll
            for (int i = 0; i < 4; i++)
#pragma unroll
                for (int j = 0; j < 4; j++) O[i][j] += pv[i] * vv[j];
        }
        __syncthreads();
    }
#pragma unroll
    for (int i = 0; i < 4; i++)
#pragma unroll
        for (int j = 0; j < 4; j++)
            g_attn[(size_t)(b * S_ + t0 + sr * 4 + i) * D_ + h * DH_ + tn * 4 + j] = O[i][j];
}

// ---------------- FFN gate + top-2 -------------------------------------------
__global__ void gate_kernel(const float* __restrict__ gff) {
    int row = blockIdx.x, tid = threadIdx.x; // 256 = 8 warps
    int w = tid >> 5, lane = tid & 31;
    __shared__ float lg[E_];
    if (w < E_) {
        float acc = 0.f;
        for (int d = lane; d < D_; d += 32)
            acc += g_xln2[(size_t)row * D_ + d] * gff[(size_t)d * E_ + w];
        for (int o = 16; o > 0; o >>= 1) acc += __shfl_down_sync(0xffffffffu, acc, o);
        if (lane == 0) lg[w] = acc;
    }
    __syncthreads();
    if (tid == 0) {
        int i0 = 0; float v0 = lg[0];
        for (int e = 1; e < E_; e++) if (lg[e] > v0) { v0 = lg[e]; i0 = e; }
        int i1 = -1; float v1 = -3.4e38f;
        for (int e = 0; e < E_; e++) { if (e == i0) continue; if (lg[e] > v1) { v1 = lg[e]; i1 = e; } }
        float e1 = expf(v1 - v0);
        float z = 1.f + e1;
        g_tk_idx[row * 2] = i0; g_tk_idx[row * 2 + 1] = i1;
        g_tk_prob[row * 2] = 1.f / z; g_tk_prob[row * 2 + 1] = e1 / z;
    }
}

// ---------------- capacity + deterministic slot assignment --------------------
__global__ void capacity_kernel() {
    int tid = threadIdx.x; // 256 = 8 warps, warp per expert
    int w = tid >> 5, lane = tid & 31;
    if (w < E_) {
        int e = w, c = 0;
        for (int i0 = 0; i0 < NTOK * 2; i0 += 32) {
            int i = i0 + lane;
            int idx = g_tk_idx[i];
            bool match = (idx == e);
            unsigned msk = __ballot_sync(0xffffffffu, match);
            if (match) {
                int rank = c + __popc(msk & ((1u << lane) - 1u));
                if (rank < CAP_) {
                    g_slot_token[e * CAP_ + rank] = i >> 1;
                    g_token_slot[i] = e * CAP_ + rank;
                } else {
                    g_token_slot[i] = -1;
                }
            }
            c += __popc(msk);
        }
        if (lane == 0) g_ecount[e] = (c < CAP_) ? c : CAP_;
    }
    __syncthreads();
    for (int t = tid; t < NTOK; t += 256) {
        int s0 = g_token_slot[2 * t], s1 = g_token_slot[2 * t + 1];
        float p0 = (s0 >= 0) ? g_tk_prob[2 * t]     : 0.f;
        float p1 = (s1 >= 0) ? g_tk_prob[2 * t + 1] : 0.f;
        float inv = 1.f / (p0 + p1 + 1e-9f);
        if (s0 >= 0) g_slot_w[s0] = p0 * inv;
        if (s1 >= 0) g_slot_w[s1] = p1 * inv;
    }
}

// ---------------- combine: out = x1 + f (deterministic, atomic-free) ----------
__global__ void combine_kernel(float* __restrict__ out) {
    int row = blockIdx.x, tid = threadIdx.x;
    int s0 = g_token_slot[2 * row], s1 = g_token_slot[2 * row + 1];
    for (int d = tid; d < D_; d += 256) {
        float v = g_x1[(size_t)row * D_ + d];
        if (s0 >= 0) v += g_sout[(size_t)s0 * D_ + d];
        if (s1 >= 0) v += g_sout[(size_t)s1 * D_ + d];
        out[(size_t)row * D_ + d] = v;
    }
}

// ---------------- aux losses ---------------------------------------------------
__global__ void aux_kernel(float* __restrict__ out, int out_size) {
    __shared__ float sa;
    if (threadIdx.x == 0) {
        const float scale = 0.01f / 2048.f;
        float es = 0.f;
        for (int i = 0; i < H_ * E_; i++) es += g_hard[i] * scale;
        float a1 = 0.f;
        for (int i = 0; i < H_ * E_; i++) {
            float p = (g_hard[i] * scale) / (es + 1e-9f);
            a1 += p * p;
        }
        a1 *= (float)(E_ * H_);
        float tcs = 0.f, ics = 0.f, ic[E_];
        for (int e = 0; e < E_; e++) {
            float s = 0.f; int c = g_ecount[e];
            for (int r = 0; r < c; r++) s += g_slot_w[e * CAP_ + r];
            ic[e] = s; ics += s; tcs += (float)c;
        }
        float a2 = 0.f;
        for (int e = 0; e < E_; e++) a2 += ((float)g_ecount[e] / tcs) * (ic[e] / ics);
        a2 *= (float)E_;
        sa = a1 + a2;
    }
    __syncthreads();
    for (int i = NOUT + threadIdx.x; i < out_size; i += blockDim.x) out[i] = sa;
}

// ---------------- launch -------------------------------------------------------
extern "C" void kernel_launch(void* const* d_in, const int* in_sizes, int n_in,
                              void* d_out, int out_size) {
    const float* x   = (const float*)d_in[0];
    // d_in[1] = mask (pure causal 0/-1e9, applied analytically)
    const float* Wq  = (const float*)d_in[2];
    const float* Wk  = (const float*)d_in[3];
    const float* Wv  = (const float*)d_in[4];
    const float* Wo  = (const float*)d_in[5];
    const float* Wr  = (const float*)d_in[6];
    const float* g1  = (const float*)d_in[7];
    const float* b1  = (const float*)d_in[8];
    const float* g2  = (const float*)d_in[9];
    const float* b2  = (const float*)d_in[10];
    const float* gff = (const float*)d_in[11];
    const float* W1  = (const float*)d_in[12];
    const float* W2  = (const float*)d_in[13];
    float* out = (float*)d_out;

    float *p_xln, *p_x1, *p_xln2;
    cudaGetSymbolAddress((void**)&p_xln,  g_xln);
    cudaGetSymbolAddress((void**)&p_x1,   g_x1);
    cudaGetSymbolAddress((void**)&p_xln2, g_xln2);

    const int pass2_smem = (4 * 64 * 65 + 128) * (int)sizeof(float);
    cudaFuncSetAttribute(attn_pass2, cudaFuncAttributeMaxDynamicSharedMemorySize, pass2_smem);

    zero_hard<<<1, 128>>>();
    ln_kernel<<<NTOK, 256>>>(x, g1, b1, p_xln);
    gemm_big<0><<<dim3(D_ / TN, NTOK / TM, 2), 256>>>(Wq, Wk);   // Q and K fused
    router_kernel<<<NTOK, 128>>>(Wr);
    vsel_kernel<<<NTOK, 384>>>(Wv);
    attn_pass1<<<dim3(S_ / 64, H_, B_), 256>>>();
    attn_pass2<<<dim3(S_ / 64, H_, B_), 256, pass2_smem>>>();
    osel_kernel<<<NTOK, 384>>>(Wo, x);
    ln_kernel<<<NTOK, 256>>>(p_x1, g2, b2, p_xln2);
    gate_kernel<<<NTOK, 256>>>(gff);
    capacity_kernel<<<1, 256>>>();
    gemm_big<1><<<dim3(DFF_ / TN, (CAP_ + TM - 1) / TM, E_), 256>>>(W1, nullptr);
    gemm_big<2><<<dim3(D_ / TN, (CAP_ + TM - 1) / TM, E_), 256>>>(W2, nullptr);
    combine_kernel<<<NTOK, 256>>>(out);
    if (out_size > NOUT) aux_kernel<<<1, 256>>>(out, out_size);
}

// round 5
// speedup vs baseline: 1.5521x; 1.5521x over previous
#include <cuda_runtime.h>
#include <math.h>

#define B_ 2
#define S_ 1024
#define D_ 768
#define H_ 12
#define E_ 8
#define DH_ 64
#define DFF_ 2048
#define NTOK (B_*S_)
#define CAP_ 320
#define NOUT (NTOK*D_)

// ---------------- scratch (device globals; no allocation allowed) -------------
__device__ float g_xln [NTOK*D_];
__device__ float g_q   [NTOK*D_];
__device__ float g_k   [NTOK*D_];
__device__ float g_vsel[NTOK*D_];
__device__ float g_attn[NTOK*D_];
__device__ float g_x1  [NTOK*D_];
__device__ float g_xln2[NTOK*D_];
__device__ int   g_eidx[NTOK*H_];
__device__ int   g_hard[H_*E_];
__device__ float g_m[B_*H_*S_];
__device__ float g_l[B_*H_*S_];
__device__ int   g_tk_idx[NTOK*2];
__device__ float g_tk_prob[NTOK*2];
__device__ int   g_token_slot[NTOK*2];
__device__ int   g_slot_token[E_*CAP_];
__device__ float g_slot_w[E_*CAP_];
__device__ int   g_ecount[E_];
__device__ float g_hbuf[E_*CAP_*DFF_];   // zero-init; rows >= count stay zero
__device__ float g_sout[E_*CAP_*D_];

// ---------------- packed f32x2 helpers ----------------------------------------
typedef unsigned long long u64t;

__device__ __forceinline__ void fma2_step(const float4 a4, const float4 b4, u64t acc[4][2]) {
    u64t bl, bh, ad;
    asm("mov.b64 %0,{%1,%2};" : "=l"(bl) : "f"(b4.x), "f"(b4.y));
    asm("mov.b64 %0,{%1,%2};" : "=l"(bh) : "f"(b4.z), "f"(b4.w));
    float av[4] = { a4.x, a4.y, a4.z, a4.w };
#pragma unroll
    for (int i = 0; i < 4; i++) {
        asm("mov.b64 %0,{%1,%1};" : "=l"(ad) : "f"(av[i]));
        asm("fma.rn.f32x2 %0,%1,%2,%0;" : "+l"(acc[i][0]) : "l"(ad), "l"(bl));
        asm("fma.rn.f32x2 %0,%1,%2,%0;" : "+l"(acc[i][1]) : "l"(ad), "l"(bh));
    }
}
__device__ __forceinline__ void unpack2(u64t v, float& lo, float& hi) {
    asm("mov.b64 {%0,%1},%2;" : "=f"(lo), "=f"(hi) : "l"(v));
}

// ---------------- LayerNorm ---------------------------------------------------
__global__ void ln_kernel(const float* __restrict__ x, const float* __restrict__ g,
                          const float* __restrict__ b, float* __restrict__ out) {
    int row = blockIdx.x, tid = threadIdx.x;
    const float* xr = x + (size_t)row * D_;
    float s = 0.f, s2 = 0.f;
    for (int d = tid; d < D_; d += 256) { float v = xr[d]; s += v; s2 += v * v; }
    for (int o = 16; o > 0; o >>= 1) {
        s  += __shfl_down_sync(0xffffffffu, s,  o);
        s2 += __shfl_down_sync(0xffffffffu, s2, o);
    }
    __shared__ float sh[8], sh2[8];
    int w = tid >> 5, lane = tid & 31;
    if (lane == 0) { sh[w] = s; sh2[w] = s2; }
    __syncthreads();
    __shared__ float smean, sinv;
    if (tid == 0) {
        float a = 0.f, a2 = 0.f;
        for (int i = 0; i < 8; i++) { a += sh[i]; a2 += sh2[i]; }
        float mean = a / D_;
        float var  = a2 / D_ - mean * mean;
        smean = mean; sinv = rsqrtf(var + 1e-5f);
    }
    __syncthreads();
    float mean = smean, inv = sinv;
    for (int d = tid; d < D_; d += 256)
        out[(size_t)row * D_ + d] = (xr[d] - mean) * inv * g[d] + b[d];
}

// ---------------- SGEMM 64x64, f32x2 packed core ------------------------------
__global__ void sgemm_nn(const float* __restrict__ A, const float* __restrict__ Bm,
                         float* __restrict__ C, int M, int N, int K) {
    __shared__ __align__(16) float As[16][68];
    __shared__ __align__(16) float Bs[16][64];
    int tid = threadIdx.x;
    int m0 = blockIdx.y * 64, n0 = blockIdx.x * 64;
    int rm = tid >> 4, cn = tid & 15;
    int ar = tid >> 2, ac = (tid & 3) << 2;
    int br = tid >> 4, bc = (tid & 15) << 2;
    u64t acc[4][2] = {};
    for (int k0 = 0; k0 < K; k0 += 16) {
        float4 a = *(const float4*)(A + (size_t)(m0 + ar) * K + k0 + ac);
        As[ac + 0][ar] = a.x; As[ac + 1][ar] = a.y;
        As[ac + 2][ar] = a.z; As[ac + 3][ar] = a.w;
        *(float4*)&Bs[br][bc] = *(const float4*)(Bm + (size_t)(k0 + br) * N + n0 + bc);
        __syncthreads();
#pragma unroll
        for (int k = 0; k < 16; k++) {
            float4 a4 = *(const float4*)&As[k][rm * 4];
            float4 b4 = *(const float4*)&Bs[k][cn * 4];
            fma2_step(a4, b4, acc);
        }
        __syncthreads();
    }
#pragma unroll
    for (int i = 0; i < 4; i++) {
        float4 o;
        unpack2(acc[i][0], o.x, o.y);
        unpack2(acc[i][1], o.z, o.w);
        *(float4*)(C + (size_t)(m0 + rm * 4 + i) * N + n0 + cn * 4) = o;
    }
}

// ---------------- attention router: argmax expert per (token, head) -----------
__global__ void zero_hard() { int i = threadIdx.x; if (i < H_ * E_) g_hard[i] = 0; }

__global__ void router_kernel(const float* __restrict__ Wr) {
    int row = blockIdx.x, tid = threadIdx.x; // 128
    __shared__ float xr[D_];
    __shared__ float lg[H_ * E_];
    for (int d = tid; d < D_; d += 128) xr[d] = g_xln[(size_t)row * D_ + d];
    __syncthreads();
    if (tid < H_ * E_) {
        float a0 = 0.f, a1 = 0.f, a2 = 0.f, a3 = 0.f;
        for (int d = 0; d < D_; d += 4) {
            a0 += xr[d + 0] * Wr[(size_t)(d + 0) * (H_ * E_) + tid];
            a1 += xr[d + 1] * Wr[(size_t)(d + 1) * (H_ * E_) + tid];
            a2 += xr[d + 2] * Wr[(size_t)(d + 2) * (H_ * E_) + tid];
            a3 += xr[d + 3] * Wr[(size_t)(d + 3) * (H_ * E_) + tid];
        }
        lg[tid] = (a0 + a1) + (a2 + a3);
    }
    __syncthreads();
    if (tid < H_) {
        int h = tid;
        float best = lg[h * E_]; int bi = 0;
        for (int e = 1; e < E_; e++) { float v = lg[h * E_ + e]; if (v > best) { best = v; bi = e; } }
        g_eidx[row * H_ + h] = bi;
        atomicAdd(&g_hard[h * E_ + bi], 1);
    }
}

// ---------------- per (token, head) expert matvecs ----------------------------
__global__ void vsel_kernel(const float* __restrict__ Wv) {
    int row = blockIdx.x, tid = threadIdx.x; // 384 = 12 warps
    int h = tid >> 5, lane = tid & 31;
    int e = g_eidx[row * H_ + h];
    const float* wv = Wv + (size_t)(h * E_ + e) * DH_ * DH_;
    const float* xh = g_xln + (size_t)row * D_ + h * DH_;
    float a0 = 0.f, a1 = 0.f, b0 = 0.f, b1 = 0.f;
    for (int d = 0; d < DH_; d += 2) {
        float x0 = xh[d], x1 = xh[d + 1];
        a0 += x0 * wv[d * DH_ + lane];
        b0 += x0 * wv[d * DH_ + lane + 32];
        a1 += x1 * wv[(d + 1) * DH_ + lane];
        b1 += x1 * wv[(d + 1) * DH_ + lane + 32];
    }
    g_vsel[(size_t)row * D_ + h * DH_ + lane]      = a0 + a1;
    g_vsel[(size_t)row * D_ + h * DH_ + lane + 32] = b0 + b1;
}

__global__ void osel_kernel(const float* __restrict__ Wo, const float* __restrict__ x) {
    int row = blockIdx.x, tid = threadIdx.x; // 384
    int h = tid >> 5, lane = tid & 31;
    int e = g_eidx[row * H_ + h];
    const float* wo = Wo + (size_t)(h * E_ + e) * DH_ * DH_;
    const float* af = g_attn + (size_t)row * D_ + h * DH_;
    float a0 = 0.f, a1 = 0.f, b0 = 0.f, b1 = 0.f;
    for (int f = 0; f < DH_; f += 2) {
        float v0 = af[f], v1 = af[f + 1];
        a0 += v0 * wo[f * DH_ + lane];
        b0 += v0 * wo[f * DH_ + lane + 32];
        a1 += v1 * wo[(f + 1) * DH_ + lane];
        b1 += v1 * wo[(f + 1) * DH_ + lane + 32];
    }
    size_t o0 = (size_t)row * D_ + h * DH_ + lane;
    g_x1[o0]      = x[o0]      + a0 + a1;
    g_x1[o0 + 32] = x[o0 + 32] + b0 + b1;
}

// ---------------- attention pass 1: exact softmax row stats (m_s, l_s) --------
// Q,K staged TRANSPOSED (d-major) so fragments are float4 loads.
__global__ void attn_pass1() {
    int s0 = blockIdx.x * 64;
    int h = blockIdx.y, b = blockIdx.z;
    int tid = threadIdx.x;
    __shared__ __align__(16) float Qt[64][68];
    __shared__ __align__(16) float Kt[64][68];
    __shared__ float red[64][16];
    __shared__ float sm[64], sl[64], sal[64];
    const float* qb = g_q + (size_t)b * S_ * D_ + h * DH_;
    const float* kb = g_k + (size_t)b * S_ * D_ + h * DH_;
#pragma unroll
    for (int i = 0; i < 16; i++) {
        int idx = tid + i * 256; int r = idx >> 6, d = idx & 63;
        Qt[d][r] = qb[(size_t)(s0 + r) * D_ + d];
    }
    if (tid < 64) { sm[tid] = -INFINITY; sl[tid] = 0.f; }
    __syncthreads();
    int rm = tid >> 4, cn = tid & 15;
    for (int t0 = 0; t0 <= s0; t0 += 64) {
#pragma unroll
        for (int i = 0; i < 16; i++) {
            int idx = tid + i * 256; int r = idx >> 6, d = idx & 63;
            Kt[d][r] = kb[(size_t)(t0 + r) * D_ + d];
        }
        __syncthreads();
        u64t acc[4][2] = {};
#pragma unroll 4
        for (int d = 0; d < 64; d++) {
            float4 q4 = *(const float4*)&Qt[d][rm * 4];
            float4 k4 = *(const float4*)&Kt[d][cn * 4];
            fma2_step(q4, k4, acc);
        }
        float sv[4][4];
#pragma unroll
        for (int i = 0; i < 4; i++) {
            unpack2(acc[i][0], sv[i][0], sv[i][1]);
            unpack2(acc[i][1], sv[i][2], sv[i][3]);
        }
#pragma unroll
        for (int i = 0; i < 4; i++) {
            int gs = s0 + rm * 4 + i;
            float mx = -INFINITY;
#pragma unroll
            for (int j = 0; j < 4; j++) {
                int gt = t0 + cn * 4 + j;
                sv[i][j] = sv[i][j] * 0.125f + ((gt <= gs) ? 0.f : -1e9f);
                mx = fmaxf(mx, sv[i][j]);
            }
            red[rm * 4 + i][cn] = mx;
        }
        __syncthreads();
        if (tid < 64) {
            float mt = red[tid][0];
            for (int c = 1; c < 16; c++) mt = fmaxf(mt, red[tid][c]);
            float mo = sm[tid], mn = fmaxf(mo, mt);
            sm[tid] = mn; sal[tid] = __expf(mo - mn);
        }
        __syncthreads();
#pragma unroll
        for (int i = 0; i < 4; i++) {
            float m = sm[rm * 4 + i];
            float s = 0.f;
#pragma unroll
            for (int j = 0; j < 4; j++) s += __expf(sv[i][j] - m);
            red[rm * 4 + i][cn] = s;
        }
        __syncthreads();
        if (tid < 64) {
            float s = 0.f;
            for (int c = 0; c < 16; c++) s += red[tid][c];
            sl[tid] = sl[tid] * sal[tid] + s;
        }
        __syncthreads();
    }
    if (tid < 64) {
        int o = (b * H_ + h) * S_ + s0 + tid;
        g_m[o] = sm[tid]; g_l[o] = sl[tid];
    }
}

// ---------------- attention pass 2: out[t] = sum_{s>=t} P[s,t] * v[s] ---------
#define P2_ROW 68
__global__ void attn_pass2() {
    extern __shared__ __align__(16) float dsm[];
    float (*Kt)[P2_ROW] = (float(*)[P2_ROW])dsm;                     // transposed [d][t]
    float (*Qt)[P2_ROW] = (float(*)[P2_ROW])(dsm + 64 * P2_ROW);     // transposed [d][s]
    float (*Vs)[P2_ROW] = (float(*)[P2_ROW])(dsm + 2 * 64 * P2_ROW); // row-major [s][f]
    float (*Ps)[P2_ROW] = (float(*)[P2_ROW])(dsm + 3 * 64 * P2_ROW); // row-major [s][t]
    float* srm  = dsm + 4 * 64 * P2_ROW;
    float* sinv = srm + 64;
    int t0 = blockIdx.x * 64;
    int h = blockIdx.y, b = blockIdx.z;
    int tid = threadIdx.x;
    const float* qb = g_q    + (size_t)b * S_ * D_ + h * DH_;
    const float* kb = g_k    + (size_t)b * S_ * D_ + h * DH_;
    const float* vb = g_vsel + (size_t)b * S_ * D_ + h * DH_;
#pragma unroll
    for (int i = 0; i < 16; i++) {
        int idx = tid + i * 256; int r = idx >> 6, d = idx & 63;
        Kt[d][r] = kb[(size_t)(t0 + r) * D_ + d];
    }
    u64t O2[4][2] = {};
    int sr = tid >> 4, tn = tid & 15;
    for (int st0 = t0; st0 < S_; st0 += 64) {
#pragma unroll
        for (int i = 0; i < 16; i++) {
            int idx = tid + i * 256; int r = idx >> 6, d = idx & 63;
            Qt[d][r] = qb[(size_t)(st0 + r) * D_ + d];
            Vs[r][d] = vb[(size_t)(st0 + r) * D_ + d];
        }
        if (tid < 64) {
            int o = (b * H_ + h) * S_ + st0 + tid;
            srm[tid] = g_m[o]; sinv[tid] = 1.f / g_l[o];
        }
        __syncthreads();
        u64t acc[4][2] = {};
#pragma unroll 4
        for (int d = 0; d < 64; d++) {
            float4 q4 = *(const float4*)&Qt[d][sr * 4];
            float4 k4 = *(const float4*)&Kt[d][tn * 4];
            fma2_step(q4, k4, acc);
        }
        float sv[4][4];
#pragma unroll
        for (int i = 0; i < 4; i++) {
            unpack2(acc[i][0], sv[i][0], sv[i][1]);
            unpack2(acc[i][1], sv[i][2], sv[i][3]);
        }
#pragma unroll
        for (int i = 0; i < 4; i++) {
            int gs = st0 + sr * 4 + i;
            float m = srm[sr * 4 + i], iv = sinv[sr * 4 + i];
#pragma unroll
            for (int j = 0; j < 4; j++) {
                int gt = t0 + tn * 4 + j;
                float p = (gt <= gs) ? __expf(sv[i][j] * 0.125f - m) * iv : 0.f;
                Ps[sr * 4 + i][tn * 4 + j] = p;
            }
        }
        __syncthreads();
#pragma unroll 4
        for (int s = 0; s < 64; s++) {
            float4 p4 = *(const float4*)&Ps[s][sr * 4];  // P(s, t=sr*4..)
            float4 v4 = *(const float4*)&Vs[s][tn * 4];  // V(s, f=tn*4..)
            fma2_step(p4, v4, O2);
        }
        __syncthreads();
    }
    float O[4][4];
#pragma unroll
    for (int i = 0; i < 4; i++) {
        unpack2(O2[i][0], O[i][0], O[i][1]);
        unpack2(O2[i][1], O[i][2], O[i][3]);
    }
#pragma unroll
    for (int i = 0; i < 4; i++)
        *(float4*)(g_attn + (size_t)(b * S_ + t0 + sr * 4 + i) * D_ + h * DH_ + tn * 4)
            = make_float4(O[i][0], O[i][1], O[i][2], O[i][3]);
}

// ---------------- FFN gate + top-2 -------------------------------------------
__global__ void gate_kernel(const float* __restrict__ gff) {
    int row = blockIdx.x, tid = threadIdx.x; // 256 = 8 warps
    int w = tid >> 5, lane = tid & 31;
    __shared__ float lg[E_];
    if (w < E_) {
        float acc = 0.f;
        for (int d = lane; d < D_; d += 32)
            acc += g_xln2[(size_t)row * D_ + d] * gff[(size_t)d * E_ + w];
        for (int o = 16; o > 0; o >>= 1) acc += __shfl_down_sync(0xffffffffu, acc, o);
        if (lane == 0) lg[w] = acc;
    }
    __syncthreads();
    if (tid == 0) {
        int i0 = 0; float v0 = lg[0];
        for (int e = 1; e < E_; e++) if (lg[e] > v0) { v0 = lg[e]; i0 = e; }
        int i1 = -1; float v1 = -3.4e38f;
        for (int e = 0; e < E_; e++) { if (e == i0) continue; if (lg[e] > v1) { v1 = lg[e]; i1 = e; } }
        float e1 = expf(v1 - v0);
        float z = 1.f + e1;
        g_tk_idx[row * 2] = i0; g_tk_idx[row * 2 + 1] = i1;
        g_tk_prob[row * 2] = 1.f / z; g_tk_prob[row * 2 + 1] = e1 / z;
    }
}

// ---------------- capacity + deterministic slot assignment --------------------
__global__ void capacity_kernel() {
    int tid = threadIdx.x; // 256 = 8 warps, warp per expert
    int w = tid >> 5, lane = tid & 31;
    if (w < E_) {
        int e = w, c = 0;
        for (int i0 = 0; i0 < NTOK * 2; i0 += 32) {
            int i = i0 + lane;
            int idx = g_tk_idx[i];
            bool match = (idx == e);
            unsigned msk = __ballot_sync(0xffffffffu, match);
            if (match) {
                int rank = c + __popc(msk & ((1u << lane) - 1u));
                if (rank < CAP_) {
                    g_slot_token[e * CAP_ + rank] = i >> 1;
                    g_token_slot[i] = e * CAP_ + rank;
                } else {
                    g_token_slot[i] = -1;
                }
            }
            c += __popc(msk);
        }
        if (lane == 0) g_ecount[e] = (c < CAP_) ? c : CAP_;
    }
    __syncthreads();
    for (int t = tid; t < NTOK; t += 256) {
        int s0 = g_token_slot[2 * t], s1 = g_token_slot[2 * t + 1];
        float p0 = (s0 >= 0) ? g_tk_prob[2 * t]     : 0.f;
        float p1 = (s1 >= 0) ? g_tk_prob[2 * t + 1] : 0.f;
        float inv = 1.f / (p0 + p1 + 1e-9f);
        if (s0 >= 0) g_slot_w[s0] = p0 * inv;
        if (s1 >= 0) g_slot_w[s1] = p1 * inv;
    }
}

// ---------------- FFN GEMM1 (gathered rows, relu), f32x2 core ------------------
__global__ void ffn_gemm1(const float* __restrict__ W1) {
    int e = blockIdx.z;
    int count = g_ecount[e];
    int m0 = blockIdx.y * 64;
    if (m0 >= count) return;
    int n0 = blockIdx.x * 64;
    const float* Bm = W1 + (size_t)e * D_ * DFF_;
    __shared__ __align__(16) float As[16][68];
    __shared__ __align__(16) float Bs[16][64];
    int tid = threadIdx.x;
    int rm = tid >> 4, cn = tid & 15;
    int ar = tid >> 2, ac = (tid & 3) << 2;
    int br = tid >> 4, bc = (tid & 15) << 2;
    int arow = m0 + ar;
    const float* Arow = (arow < count) ? (g_xln2 + (size_t)g_slot_token[e * CAP_ + arow] * D_) : nullptr;
    u64t acc[4][2] = {};
    for (int k0 = 0; k0 < D_; k0 += 16) {
        float4 a = Arow ? *(const float4*)(Arow + k0 + ac) : make_float4(0.f, 0.f, 0.f, 0.f);
        As[ac + 0][ar] = a.x; As[ac + 1][ar] = a.y;
        As[ac + 2][ar] = a.z; As[ac + 3][ar] = a.w;
        *(float4*)&Bs[br][bc] = *(const float4*)(Bm + (size_t)(k0 + br) * DFF_ + n0 + bc);
        __syncthreads();
#pragma unroll
        for (int k = 0; k < 16; k++) {
            float4 a4 = *(const float4*)&As[k][rm * 4];
            float4 b4 = *(const float4*)&Bs[k][cn * 4];
            fma2_step(a4, b4, acc);
        }
        __syncthreads();
    }
#pragma unroll
    for (int i = 0; i < 4; i++) {
        int m = m0 + rm * 4 + i;
        if (m < count) {
            float4 o;
            unpack2(acc[i][0], o.x, o.y);
            unpack2(acc[i][1], o.z, o.w);
            o.x = fmaxf(o.x, 0.f); o.y = fmaxf(o.y, 0.f);
            o.z = fmaxf(o.z, 0.f); o.w = fmaxf(o.w, 0.f);
            *(float4*)(g_hbuf + (size_t)(e * CAP_ + m) * DFF_ + n0 + cn * 4) = o;
        }
    }
}

// ---------------- FFN GEMM2 (scaled by slot weight), f32x2 core ----------------
__global__ void ffn_gemm2(const float* __restrict__ W2) {
    int e = blockIdx.z;
    int count = g_ecount[e];
    int m0 = blockIdx.y * 64;
    if (m0 >= count) return;
    int n0 = blockIdx.x * 64;
    const float* Am = g_hbuf + (size_t)e * CAP_ * DFF_;
    const float* Bm = W2 + (size_t)e * DFF_ * D_;
    __shared__ __align__(16) float As[16][68];
    __shared__ __align__(16) float Bs[16][64];
    int tid = threadIdx.x;
    int rm = tid >> 4, cn = tid & 15;
    int ar = tid >> 2, ac = (tid & 3) << 2;
    int br = tid >> 4, bc = (tid & 15) << 2;
    u64t acc[4][2] = {};
    for (int k0 = 0; k0 < DFF_; k0 += 16) {
        float4 a = *(const float4*)(Am + (size_t)(m0 + ar) * DFF_ + k0 + ac);
        As[ac + 0][ar] = a.x; As[ac + 1][ar] = a.y;
        As[ac + 2][ar] = a.z; As[ac + 3][ar] = a.w;
        *(float4*)&Bs[br][bc] = *(const float4*)(Bm + (size_t)(k0 + br) * D_ + n0 + bc);
        __syncthreads();
#pragma unroll
        for (int k = 0; k < 16; k++) {
            float4 a4 = *(const float4*)&As[k][rm * 4];
            float4 b4 = *(const float4*)&Bs[k][cn * 4];
            fma2_step(a4, b4, acc);
        }
        __syncthreads();
    }
#pragma unroll
    for (int i = 0; i < 4; i++) {
        int m = m0 + rm * 4 + i;
        if (m < count) {
            float wgt = g_slot_w[e * CAP_ + m];
            float4 o;
            unpack2(acc[i][0], o.x, o.y);
            unpack2(acc[i][1], o.z, o.w);
            o.x *= wgt; o.y *= wgt; o.z *= wgt; o.w *= wgt;
            *(float4*)(g_sout + (size_t)(e * CAP_ + m) * D_ + n0 + cn * 4) = o;
        }
    }
}

// ---------------- combine: out = x1 + f (deterministic, atomic-free) ----------
__global__ void combine_kernel(float* __restrict__ out) {
    int row = blockIdx.x, tid = threadIdx.x;
    int s0 = g_token_slot[2 * row], s1 = g_token_slot[2 * row + 1];
    for (int d = tid; d < D_; d += 256) {
        float v = g_x1[(size_t)row * D_ + d];
        if (s0 >= 0) v += g_sout[(size_t)s0 * D_ + d];
        if (s1 >= 0) v += g_sout[(size_t)s1 * D_ + d];
        out[(size_t)row * D_ + d] = v;
    }
}

// ---------------- aux losses ---------------------------------------------------
__global__ void aux_kernel(float* __restrict__ out, int out_size) {
    __shared__ float sa;
    if (threadIdx.x == 0) {
        const float scale = 0.01f / 2048.f;
        float es = 0.f;
        for (int i = 0; i < H_ * E_; i++) es += g_hard[i] * scale;
        float a1 = 0.f;
        for (int i = 0; i < H_ * E_; i++) {
            float p = (g_hard[i] * scale) / (es + 1e-9f);
            a1 += p * p;
        }
        a1 *= (float)(E_ * H_);
        float tcs = 0.f, ics = 0.f, ic[E_];
        for (int e = 0; e < E_; e++) {
            float s = 0.f; int c = g_ecount[e];
            for (int r = 0; r < c; r++) s += g_slot_w[e * CAP_ + r];
            ic[e] = s; ics += s; tcs += (float)c;
        }
        float a2 = 0.f;
        for (int e = 0; e < E_; e++) a2 += ((float)g_ecount[e] / tcs) * (ic[e] / ics);
        a2 *= (float)E_;
        sa = a1 + a2;
    }
    __syncthreads();
    for (int i = NOUT + threadIdx.x; i < out_size; i += blockDim.x) out[i] = sa;
}

// ---------------- launch -------------------------------------------------------
extern "C" void kernel_launch(void* const* d_in, const int* in_sizes, int n_in,
                              void* d_out, int out_size) {
    const float* x   = (const float*)d_in[0];
    // d_in[1] = mask (pure causal 0/-1e9, applied analytically)
    const float* Wq  = (const float*)d_in[2];
    const float* Wk  = (const float*)d_in[3];
    const float* Wv  = (const float*)d_in[4];
    const float* Wo  = (const float*)d_in[5];
    const float* Wr  = (const float*)d_in[6];
    const float* g1  = (const float*)d_in[7];
    const float* b1  = (const float*)d_in[8];
    const float* g2  = (const float*)d_in[9];
    const float* b2  = (const float*)d_in[10];
    const float* gff = (const float*)d_in[11];
    const float* W1  = (const float*)d_in[12];
    const float* W2  = (const float*)d_in[13];
    float* out = (float*)d_out;

    float *p_xln, *p_q, *p_k, *p_x1, *p_xln2;
    cudaGetSymbolAddress((void**)&p_xln,  g_xln);
    cudaGetSymbolAddress((void**)&p_q,    g_q);
    cudaGetSymbolAddress((void**)&p_k,    g_k);
    cudaGetSymbolAddress((void**)&p_x1,   g_x1);
    cudaGetSymbolAddress((void**)&p_xln2, g_xln2);

    const int pass2_smem = (4 * 64 * P2_ROW + 128) * (int)sizeof(float);
    cudaFuncSetAttribute(attn_pass2, cudaFuncAttributeMaxDynamicSharedMemorySize, pass2_smem);

    zero_hard<<<1, 128>>>();
    ln_kernel<<<NTOK, 256>>>(x, g1, b1, p_xln);
    sgemm_nn<<<dim3(D_ / 64, NTOK / 64), 256>>>(p_xln, Wq, p_q, NTOK, D_, D_);
    sgemm_nn<<<dim3(D_ / 64, NTOK / 64), 256>>>(p_xln, Wk, p_k, NTOK, D_, D_);
    router_kernel<<<NTOK, 128>>>(Wr);
    vsel_kernel<<<NTOK, 384>>>(Wv);
    attn_pass1<<<dim3(S_ / 64, H_, B_), 256>>>();
    attn_pass2<<<dim3(S_ / 64, H_, B_), 256, pass2_smem>>>();
    osel_kernel<<<NTOK, 384>>>(Wo, x);
    ln_kernel<<<NTOK, 256>>>(p_x1, g2, b2, p_xln2);
    gate_kernel<<<NTOK, 256>>>(gff);
    capacity_kernel<<<1, 256>>>();
    ffn_gemm1<<<dim3(DFF_ / 64, CAP_ / 64, E_), 256>>>(W1);
    ffn_gemm2<<<dim3(D_ / 64, CAP_ / 64, E_), 256>>>(W2);
    combine_kernel<<<NTOK, 256>>>(out);
    if (out_size > NOUT) aux_kernel<<<1, 256>>>(out, out_size);
}

// round 6
// speedup vs baseline: 2.1259x; 1.3696x over previous
#include <cuda_runtime.h>
#include <math.h>

#define B_ 2
#define S_ 1024
#define D_ 768
#define H_ 12
#define E_ 8
#define DH_ 64
#define DFF_ 2048
#define NTOK (B_*S_)
#define CAP_ 320
#define NOUT (NTOK*D_)

// ---------------- scratch (device globals; no allocation allowed) -------------
__device__ float g_xln [NTOK*D_];
__device__ float g_q   [NTOK*D_];
__device__ float g_k   [NTOK*D_];
__device__ float g_vsel[NTOK*D_];
__device__ float g_attn[NTOK*D_];
__device__ float g_x1  [NTOK*D_];
__device__ float g_xln2[NTOK*D_];
__device__ int   g_eidx[NTOK*H_];
__device__ int   g_hard[H_*E_];
__device__ float g_m[B_*H_*S_];
__device__ float g_l[B_*H_*S_];
__device__ int   g_tk_idx[NTOK*2];
__device__ float g_tk_prob[NTOK*2];
__device__ int   g_token_slot[NTOK*2];
__device__ int   g_slot_token[E_*CAP_];
__device__ float g_slot_w[E_*CAP_];
__device__ int   g_ecount[E_];
__device__ float g_hbuf[E_*CAP_*DFF_];
__device__ float g_sout[E_*CAP_*D_];

// ---------------- packed f32x2 helpers (attention) -----------------------------
typedef unsigned long long u64t;

__device__ __forceinline__ void fma2_step(const float4 a4, const float4 b4, u64t acc[4][2]) {
    u64t bl, bh, ad;
    asm("mov.b64 %0,{%1,%2};" : "=l"(bl) : "f"(b4.x), "f"(b4.y));
    asm("mov.b64 %0,{%1,%2};" : "=l"(bh) : "f"(b4.z), "f"(b4.w));
    float av[4] = { a4.x, a4.y, a4.z, a4.w };
#pragma unroll
    for (int i = 0; i < 4; i++) {
        asm("mov.b64 %0,{%1,%1};" : "=l"(ad) : "f"(av[i]));
        asm("fma.rn.f32x2 %0,%1,%2,%0;" : "+l"(acc[i][0]) : "l"(ad), "l"(bl));
        asm("fma.rn.f32x2 %0,%1,%2,%0;" : "+l"(acc[i][1]) : "l"(ad), "l"(bh));
    }
}
__device__ __forceinline__ void unpack2(u64t v, float& lo, float& hi) {
    asm("mov.b64 {%0,%1},%2;" : "=f"(lo), "=f"(hi) : "l"(v));
}

// ---------------- tf32 tensor-core helpers -------------------------------------
__device__ __forceinline__ unsigned to_tf32(float f) {
    unsigned u; asm("cvt.rna.tf32.f32 %0,%1;" : "=r"(u) : "f"(f)); return u;
}
__device__ __forceinline__ void mma_tf32(float c[4], const unsigned a[4], const unsigned b[2]) {
    asm("mma.sync.aligned.m16n8k8.row.col.f32.tf32.tf32.f32 "
        "{%0,%1,%2,%3},{%4,%5,%6,%7},{%8,%9},{%0,%1,%2,%3};"
        : "+f"(c[0]), "+f"(c[1]), "+f"(c[2]), "+f"(c[3])
        : "r"(a[0]), "r"(a[1]), "r"(a[2]), "r"(a[3]), "r"(b[0]), "r"(b[1]));
}

// ---------------- LayerNorm ---------------------------------------------------
__global__ void ln_kernel(const float* __restrict__ x, const float* __restrict__ g,
                          const float* __restrict__ b, float* __restrict__ out) {
    int row = blockIdx.x, tid = threadIdx.x;
    const float* xr = x + (size_t)row * D_;
    float s = 0.f, s2 = 0.f;
    for (int d = tid; d < D_; d += 256) { float v = xr[d]; s += v; s2 += v * v; }
    for (int o = 16; o > 0; o >>= 1) {
        s  += __shfl_down_sync(0xffffffffu, s,  o);
        s2 += __shfl_down_sync(0xffffffffu, s2, o);
    }
    __shared__ float sh[8], sh2[8];
    int w = tid >> 5, lane = tid & 31;
    if (lane == 0) { sh[w] = s; sh2[w] = s2; }
    __syncthreads();
    __shared__ float smean, sinv;
    if (tid == 0) {
        float a = 0.f, a2 = 0.f;
        for (int i = 0; i < 8; i++) { a += sh[i]; a2 += sh2[i]; }
        float mean = a / D_;
        float var  = a2 / D_ - mean * mean;
        smean = mean; sinv = rsqrtf(var + 1e-5f);
    }
    __syncthreads();
    float mean = smean, inv = sinv;
    for (int d = tid; d < D_; d += 256)
        out[(size_t)row * D_ + d] = (xr[d] - mean) * inv * g[d] + b[d];
}

// ---------------- tf32 tensor-core GEMM, 128x64x16 tiles -----------------------
// MODE 0: Q/K projection.  z=0 -> B=P0(Wq), C=g_q ; z=1 -> B=P1(Wk), C=g_k.
// MODE 1: FFN GEMM1 (gathered A rows, ReLU). z=e. B=W1[e]. C=g_hbuf[e].
// MODE 2: FFN GEMM2 (slot-weight scale).     z=e. B=W2[e]. C=g_sout[e].
#define ASTRIDE 20
#define BSTRIDE 72
template<int MODE>
__global__ __launch_bounds__(256)
void gemm_tf32(const float* __restrict__ P0, const float* __restrict__ P1) {
    __shared__ __align__(16) unsigned As[128 * ASTRIDE];
    __shared__ __align__(16) unsigned Bs[16 * BSTRIDE];

    const int tid = threadIdx.x, wid = tid >> 5, lane = tid & 31;
    const int e  = blockIdx.z;
    const int m0 = blockIdx.y * 128;
    const int n0 = blockIdx.x * 64;

    int N, K, count;
    const float* Bm;
    float* C;
    const float* Abase;
    if (MODE == 0) {
        N = D_; K = D_; count = NTOK;
        Bm = (e == 0) ? P0 : P1;
        C  = (e == 0) ? g_q : g_k;
        Abase = g_xln;
    } else if (MODE == 1) {
        N = DFF_; K = D_; count = g_ecount[e];
        if (count <= 0 || m0 >= count) return;
        Bm = P0 + (size_t)e * D_ * DFF_;
        C  = g_hbuf + (size_t)e * CAP_ * DFF_;
        Abase = g_xln2;
    } else {
        N = D_; K = DFF_; count = g_ecount[e];
        if (count <= 0 || m0 >= count) return;
        Bm = P0 + (size_t)e * DFF_ * D_;
        C  = g_sout + (size_t)e * CAP_ * D_;
        Abase = g_hbuf + (size_t)e * CAP_ * DFF_;
    }

    // staging assignments
    const int sm_r = tid >> 1;          // A tile row 0..127
    const int sm_k = (tid & 1) * 8;     // A k sub-offset {0,8}
    const int brow = tid >> 4;          // B tile row 0..15
    const int bcol = (tid & 15) * 4;    // B tile col group

    const float* Aptr;
    {
        int r = m0 + sm_r;
        if (r >= count) r = count - 1;      // clamp (results for these rows discarded)
        if (MODE == 1)
            Aptr = Abase + (size_t)g_slot_token[e * CAP_ + r] * D_ + sm_k;
        else
            Aptr = Abase + (size_t)r * K + sm_k;
    }
    const float* Bptr = Bm + (size_t)brow * N + n0 + bcol;

    // warp tile: 32x32.  4 warps along M, 2 along N.
    const int wm0 = (wid & 3) * 32;
    const int wn0 = (wid >> 2) * 32;
    const int gr = lane >> 2, gc = lane & 3;

    float acc[2][4][4];
#pragma unroll
    for (int i = 0; i < 2; i++)
#pragma unroll
        for (int j = 0; j < 4; j++)
#pragma unroll
            for (int q = 0; q < 4; q++) acc[i][j][q] = 0.f;

    for (int k0 = 0; k0 < K; k0 += 16) {
        float4 av0 = *(const float4*)(Aptr + k0);
        float4 av1 = *(const float4*)(Aptr + k0 + 4);
        float4 bv  = *(const float4*)(Bptr + (size_t)k0 * N);
        uint4 u0 = make_uint4(to_tf32(av0.x), to_tf32(av0.y), to_tf32(av0.z), to_tf32(av0.w));
        uint4 u1 = make_uint4(to_tf32(av1.x), to_tf32(av1.y), to_tf32(av1.z), to_tf32(av1.w));
        uint4 ub = make_uint4(to_tf32(bv.x),  to_tf32(bv.y),  to_tf32(bv.z),  to_tf32(bv.w));
        *(uint4*)&As[sm_r * ASTRIDE + sm_k]     = u0;
        *(uint4*)&As[sm_r * ASTRIDE + sm_k + 4] = u1;
        *(uint4*)&Bs[brow * BSTRIDE + bcol]     = ub;
        __syncthreads();
#pragma unroll
        for (int kk = 0; kk < 16; kk += 8) {
            unsigned a[2][4];
#pragma unroll
            for (int mf = 0; mf < 2; mf++) {
                int mb = wm0 + mf * 16;
                a[mf][0] = As[(mb + gr)     * ASTRIDE + kk + gc];
                a[mf][1] = As[(mb + gr + 8) * ASTRIDE + kk + gc];
                a[mf][2] = As[(mb + gr)     * ASTRIDE + kk + gc + 4];
                a[mf][3] = As[(mb + gr + 8) * ASTRIDE + kk + gc + 4];
            }
#pragma unroll
            for (int nf = 0; nf < 4; nf++) {
                int nb = wn0 + nf * 8 + gr;
                unsigned b[2];
                b[0] = Bs[(kk + gc)     * BSTRIDE + nb];
                b[1] = Bs[(kk + gc + 4) * BSTRIDE + nb];
                mma_tf32(acc[0][nf], a[0], b);
                mma_tf32(acc[1][nf], a[1], b);
            }
        }
        __syncthreads();
    }

    // ---- store ----
#pragma unroll
    for (int mf = 0; mf < 2; mf++) {
        int rbase = m0 + wm0 + mf * 16 + gr;
#pragma unroll
        for (int half = 0; half < 2; half++) {
            int r = rbase + half * 8;
            if (MODE != 0 && r >= count) continue;
            float w = 1.f;
            if (MODE == 2) w = g_slot_w[e * CAP_ + r];
#pragma unroll
            for (int nf = 0; nf < 4; nf++) {
                int cc = n0 + wn0 + nf * 8 + gc * 2;
                float v0 = acc[mf][nf][half * 2 + 0];
                float v1 = acc[mf][nf][half * 2 + 1];
                if (MODE == 1) { v0 = fmaxf(v0, 0.f); v1 = fmaxf(v1, 0.f); }
                else if (MODE == 2) { v0 *= w; v1 *= w; }
                *(float2*)(C + (size_t)r * N + cc) = make_float2(v0, v1);
            }
        }
    }
}

// ---------------- attention router: argmax expert per (token, head) -----------
__global__ void zero_hard() { int i = threadIdx.x; if (i < H_ * E_) g_hard[i] = 0; }

__global__ void router_kernel(const float* __restrict__ Wr) {
    int row = blockIdx.x, tid = threadIdx.x; // 128
    __shared__ float xr[D_];
    __shared__ float lg[H_ * E_];
    for (int d = tid; d < D_; d += 128) xr[d] = g_xln[(size_t)row * D_ + d];
    __syncthreads();
    if (tid < H_ * E_) {
        float a0 = 0.f, a1 = 0.f, a2 = 0.f, a3 = 0.f;
        for (int d = 0; d < D_; d += 4) {
            a0 += xr[d + 0] * Wr[(size_t)(d + 0) * (H_ * E_) + tid];
            a1 += xr[d + 1] * Wr[(size_t)(d + 1) * (H_ * E_) + tid];
            a2 += xr[d + 2] * Wr[(size_t)(d + 2) * (H_ * E_) + tid];
            a3 += xr[d + 3] * Wr[(size_t)(d + 3) * (H_ * E_) + tid];
        }
        lg[tid] = (a0 + a1) + (a2 + a3);
    }
    __syncthreads();
    if (tid < H_) {
        int h = tid;
        float best = lg[h * E_]; int bi = 0;
        for (int e = 1; e < E_; e++) { float v = lg[h * E_ + e]; if (v > best) { best = v; bi = e; } }
        g_eidx[row * H_ + h] = bi;
        atomicAdd(&g_hard[h * E_ + bi], 1);
    }
}

// ---------------- per (token, head) expert matvecs ----------------------------
__global__ void vsel_kernel(const float* __restrict__ Wv) {
    int row = blockIdx.x, tid = threadIdx.x; // 384 = 12 warps
    int h = tid >> 5, lane = tid & 31;
    int e = g_eidx[row * H_ + h];
    const float* wv = Wv + (size_t)(h * E_ + e) * DH_ * DH_;
    const float* xh = g_xln + (size_t)row * D_ + h * DH_;
    float a0 = 0.f, a1 = 0.f, b0 = 0.f, b1 = 0.f;
    for (int d = 0; d < DH_; d += 2) {
        float x0 = xh[d], x1 = xh[d + 1];
        a0 += x0 * wv[d * DH_ + lane];
        b0 += x0 * wv[d * DH_ + lane + 32];
        a1 += x1 * wv[(d + 1) * DH_ + lane];
        b1 += x1 * wv[(d + 1) * DH_ + lane + 32];
    }
    g_vsel[(size_t)row * D_ + h * DH_ + lane]      = a0 + a1;
    g_vsel[(size_t)row * D_ + h * DH_ + lane + 32] = b0 + b1;
}

__global__ void osel_kernel(const float* __restrict__ Wo, const float* __restrict__ x) {
    int row = blockIdx.x, tid = threadIdx.x; // 384
    int h = tid >> 5, lane = tid & 31;
    int e = g_eidx[row * H_ + h];
    const float* wo = Wo + (size_t)(h * E_ + e) * DH_ * DH_;
    const float* af = g_attn + (size_t)row * D_ + h * DH_;
    float a0 = 0.f, a1 = 0.f, b0 = 0.f, b1 = 0.f;
    for (int f = 0; f < DH_; f += 2) {
        float v0 = af[f], v1 = af[f + 1];
        a0 += v0 * wo[f * DH_ + lane];
        b0 += v0 * wo[f * DH_ + lane + 32];
        a1 += v1 * wo[(f + 1) * DH_ + lane];
        b1 += v1 * wo[(f + 1) * DH_ + lane + 32];
    }
    size_t o0 = (size_t)row * D_ + h * DH_ + lane;
    g_x1[o0]      = x[o0]      + a0 + a1;
    g_x1[o0 + 32] = x[o0 + 32] + b0 + b1;
}

// ---------------- attention pass 1: exact softmax row stats (m_s, l_s) --------
__global__ void attn_pass1() {
    int s0 = blockIdx.x * 64;
    int h = blockIdx.y, b = blockIdx.z;
    int tid = threadIdx.x;
    __shared__ __align__(16) float Qt[64][68];
    __shared__ __align__(16) float Kt[64][68];
    __shared__ float red[64][16];
    __shared__ float sm[64], sl[64], sal[64];
    const float* qb = g_q + (size_t)b * S_ * D_ + h * DH_;
    const float* kb = g_k + (size_t)b * S_ * D_ + h * DH_;
#pragma unroll
    for (int i = 0; i < 16; i++) {
        int idx = tid + i * 256; int r = idx >> 6, d = idx & 63;
        Qt[d][r] = qb[(size_t)(s0 + r) * D_ + d];
    }
    if (tid < 64) { sm[tid] = -INFINITY; sl[tid] = 0.f; }
    __syncthreads();
    int rm = tid >> 4, cn = tid & 15;
    for (int t0 = 0; t0 <= s0; t0 += 64) {
#pragma unroll
        for (int i = 0; i < 16; i++) {
            int idx = tid + i * 256; int r = idx >> 6, d = idx & 63;
            Kt[d][r] = kb[(size_t)(t0 + r) * D_ + d];
        }
        __syncthreads();
        u64t acc[4][2] = {};
#pragma unroll 4
        for (int d = 0; d < 64; d++) {
            float4 q4 = *(const float4*)&Qt[d][rm * 4];
            float4 k4 = *(const float4*)&Kt[d][cn * 4];
            fma2_step(q4, k4, acc);
        }
        float sv[4][4];
#pragma unroll
        for (int i = 0; i < 4; i++) {
            unpack2(acc[i][0], sv[i][0], sv[i][1]);
            unpack2(acc[i][1], sv[i][2], sv[i][3]);
        }
#pragma unroll
        for (int i = 0; i < 4; i++) {
            int gs = s0 + rm * 4 + i;
            float mx = -INFINITY;
#pragma unroll
            for (int j = 0; j < 4; j++) {
                int gt = t0 + cn * 4 + j;
                sv[i][j] = sv[i][j] * 0.125f + ((gt <= gs) ? 0.f : -1e9f);
                mx = fmaxf(mx, sv[i][j]);
            }
            red[rm * 4 + i][cn] = mx;
        }
        __syncthreads();
        if (tid < 64) {
            float mt = red[tid][0];
            for (int c = 1; c < 16; c++) mt = fmaxf(mt, red[tid][c]);
            float mo = sm[tid], mn = fmaxf(mo, mt);
            sm[tid] = mn; sal[tid] = __expf(mo - mn);
        }
        __syncthreads();
#pragma unroll
        for (int i = 0; i < 4; i++) {
            float m = sm[rm * 4 + i];
            float s = 0.f;
#pragma unroll
            for (int j = 0; j < 4; j++) s += __expf(sv[i][j] - m);
            red[rm * 4 + i][cn] = s;
        }
        __syncthreads();
        if (tid < 64) {
            float s = 0.f;
            for (int c = 0; c < 16; c++) s += red[tid][c];
            sl[tid] = sl[tid] * sal[tid] + s;
        }
        __syncthreads();
    }
    if (tid < 64) {
        int o = (b * H_ + h) * S_ + s0 + tid;
        g_m[o] = sm[tid]; g_l[o] = sl[tid];
    }
}

// ---------------- attention pass 2: out[t] = sum_{s>=t} P[s,t] * v[s] ---------
#define P2_ROW 68
__global__ void attn_pass2() {
    extern __shared__ __align__(16) float dsm[];
    float (*Kt)[P2_ROW] = (float(*)[P2_ROW])dsm;
    float (*Qt)[P2_ROW] = (float(*)[P2_ROW])(dsm + 64 * P2_ROW);
    float (*Vs)[P2_ROW] = (float(*)[P2_ROW])(dsm + 2 * 64 * P2_ROW);
    float (*Ps)[P2_ROW] = (float(*)[P2_ROW])(dsm + 3 * 64 * P2_ROW);
    float* srm  = dsm + 4 * 64 * P2_ROW;
    float* sinv = srm + 64;
    int t0 = blockIdx.x * 64;
    int h = blockIdx.y, b = blockIdx.z;
    int tid = threadIdx.x;
    const float* qb = g_q    + (size_t)b * S_ * D_ + h * DH_;
    const float* kb = g_k    + (size_t)b * S_ * D_ + h * DH_;
    const float* vb = g_vsel + (size_t)b * S_ * D_ + h * DH_;
#pragma unroll
    for (int i = 0; i < 16; i++) {
        int idx = tid + i * 256; int r = idx >> 6, d = idx & 63;
        Kt[d][r] = kb[(size_t)(t0 + r) * D_ + d];
    }
    u64t O2[4][2] = {};
    int sr = tid >> 4, tn = tid & 15;
    for (int st0 = t0; st0 < S_; st0 += 64) {
#pragma unroll
        for (int i = 0; i < 16; i++) {
            int idx = tid + i * 256; int r = idx >> 6, d = idx & 63;
            Qt[d][r] = qb[(size_t)(st0 + r) * D_ + d];
            Vs[r][d] = vb[(size_t)(st0 + r) * D_ + d];
        }
        if (tid < 64) {
            int o = (b * H_ + h) * S_ + st0 + tid;
            srm[tid] = g_m[o]; sinv[tid] = 1.f / g_l[o];
        }
        __syncthreads();
        u64t acc[4][2] = {};
#pragma unroll 4
        for (int d = 0; d < 64; d++) {
            float4 q4 = *(const float4*)&Qt[d][sr * 4];
            float4 k4 = *(const float4*)&Kt[d][tn * 4];
            fma2_step(q4, k4, acc);
        }
        float sv[4][4];
#pragma unroll
        for (int i = 0; i < 4; i++) {
            unpack2(acc[i][0], sv[i][0], sv[i][1]);
            unpack2(acc[i][1], sv[i][2], sv[i][3]);
        }
#pragma unroll
        for (int i = 0; i < 4; i++) {
            int gs = st0 + sr * 4 + i;
            float m = srm[sr * 4 + i], iv = sinv[sr * 4 + i];
#pragma unroll
            for (int j = 0; j < 4; j++) {
                int gt = t0 + tn * 4 + j;
                float p = (gt <= gs) ? __expf(sv[i][j] * 0.125f - m) * iv : 0.f;
                Ps[sr * 4 + i][tn * 4 + j] = p;
            }
        }
        __syncthreads();
#pragma unroll 4
        for (int s = 0; s < 64; s++) {
            float4 p4 = *(const float4*)&Ps[s][sr * 4];
            float4 v4 = *(const float4*)&Vs[s][tn * 4];
            fma2_step(p4, v4, O2);
        }
        __syncthreads();
    }
    float O[4][4];
#pragma unroll
    for (int i = 0; i < 4; i++) {
        unpack2(O2[i][0], O[i][0], O[i][1]);
        unpack2(O2[i][1], O[i][2], O[i][3]);
    }
#pragma unroll
    for (int i = 0; i < 4; i++)
        *(float4*)(g_attn + (size_t)(b * S_ + t0 + sr * 4 + i) * D_ + h * DH_ + tn * 4)
            = make_float4(O[i][0], O[i][1], O[i][2], O[i][3]);
}

// ---------------- FFN gate + top-2 -------------------------------------------
__global__ void gate_kernel(const float* __restrict__ gff) {
    int row = blockIdx.x, tid = threadIdx.x; // 256 = 8 warps
    int w = tid >> 5, lane = tid & 31;
    __shared__ float lg[E_];
    if (w < E_) {
        float acc = 0.f;
        for (int d = lane; d < D_; d += 32)
            acc += g_xln2[(size_t)row * D_ + d] * gff[(size_t)d * E_ + w];
        for (int o = 16; o > 0; o >>= 1) acc += __shfl_down_sync(0xffffffffu, acc, o);
        if (lane == 0) lg[w] = acc;
    }
    __syncthreads();
    if (tid == 0) {
        int i0 = 0; float v0 = lg[0];
        for (int e = 1; e < E_; e++) if (lg[e] > v0) { v0 = lg[e]; i0 = e; }
        int i1 = -1; float v1 = -3.4e38f;
        for (int e = 0; e < E_; e++) { if (e == i0) continue; if (lg[e] > v1) { v1 = lg[e]; i1 = e; } }
        float e1 = expf(v1 - v0);
        float z = 1.f + e1;
        g_tk_idx[row * 2] = i0; g_tk_idx[row * 2 + 1] = i1;
        g_tk_prob[row * 2] = 1.f / z; g_tk_prob[row * 2 + 1] = e1 / z;
    }
}

// ---------------- capacity + deterministic slot assignment --------------------
__global__ void capacity_kernel() {
    int tid = threadIdx.x; // 256 = 8 warps, warp per expert
    int w = tid >> 5, lane = tid & 31;
    if (w < E_) {
        int e = w, c = 0;
        for (int i0 = 0; i0 < NTOK * 2; i0 += 32) {
            int i = i0 + lane;
            int idx = g_tk_idx[i];
            bool match = (idx == e);
            unsigned msk = __ballot_sync(0xffffffffu, match);
            if (match) {
                int rank = c + __popc(msk & ((1u << lane) - 1u));
                if (rank < CAP_) {
                    g_slot_token[e * CAP_ + rank] = i >> 1;
                    g_token_slot[i] = e * CAP_ + rank;
                } else {
                    g_token_slot[i] = -1;
                }
            }
            c += __popc(msk);
        }
        if (lane == 0) g_ecount[e] = (c < CAP_) ? c : CAP_;
    }
    __syncthreads();
    for (int t = tid; t < NTOK; t += 256) {
        int s0 = g_token_slot[2 * t], s1 = g_token_slot[2 * t + 1];
        float p0 = (s0 >= 0) ? g_tk_prob[2 * t]     : 0.f;
        float p1 = (s1 >= 0) ? g_tk_prob[2 * t + 1] : 0.f;
        float inv = 1.f / (p0 + p1 + 1e-9f);
        if (s0 >= 0) g_slot_w[s0] = p0 * inv;
        if (s1 >= 0) g_slot_w[s1] = p1 * inv;
    }
}

// ---------------- combine: out = x1 + f (deterministic, atomic-free) ----------
__global__ void combine_kernel(float* __restrict__ out) {
    int row = blockIdx.x, tid = threadIdx.x;
    int s0 = g_token_slot[2 * row], s1 = g_token_slot[2 * row + 1];
    for (int d = tid; d < D_; d += 256) {
        float v = g_x1[(size_t)row * D_ + d];
        if (s0 >= 0) v += g_sout[(size_t)s0 * D_ + d];
        if (s1 >= 0) v += g_sout[(size_t)s1 * D_ + d];
        out[(size_t)row * D_ + d] = v;
    }
}

// ---------------- aux losses ---------------------------------------------------
__global__ void aux_kernel(float* __restrict__ out, int out_size) {
    __shared__ float sa;
    if (threadIdx.x == 0) {
        const float scale = 0.01f / 2048.f;
        float es = 0.f;
        for (int i = 0; i < H_ * E_; i++) es += g_hard[i] * scale;
        float a1 = 0.f;
        for (int i = 0; i < H_ * E_; i++) {
            float p = (g_hard[i] * scale) / (es + 1e-9f);
            a1 += p * p;
        }
        a1 *= (float)(E_ * H_);
        float tcs = 0.f, ics = 0.f, ic[E_];
        for (int e = 0; e < E_; e++) {
            float s = 0.f; int c = g_ecount[e];
            for (int r = 0; r < c; r++) s += g_slot_w[e * CAP_ + r];
            ic[e] = s; ics += s; tcs += (float)c;
        }
        float a2 = 0.f;
        for (int e = 0; e < E_; e++) a2 += ((float)g_ecount[e] / tcs) * (ic[e] / ics);
        a2 *= (float)E_;
        sa = a1 + a2;
    }
    __syncthreads();
    for (int i = NOUT + threadIdx.x; i < out_size; i += blockDim.x) out[i] = sa;
}

// ---------------- launch -------------------------------------------------------
extern "C" void kernel_launch(void* const* d_in, const int* in_sizes, int n_in,
                              void* d_out, int out_size) {
    const float* x   = (const float*)d_in[0];
    // d_in[1] = mask (pure causal 0/-1e9, applied analytically)
    const float* Wq  = (const float*)d_in[2];
    const float* Wk  = (const float*)d_in[3];
    const float* Wv  = (const float*)d_in[4];
    const float* Wo  = (const float*)d_in[5];
    const float* Wr  = (const float*)d_in[6];
    const float* g1  = (const float*)d_in[7];
    const float* b1  = (const float*)d_in[8];
    const float* g2  = (const float*)d_in[9];
    const float* b2  = (const float*)d_in[10];
    const float* gff = (const float*)d_in[11];
    const float* W1  = (const float*)d_in[12];
    const float* W2  = (const float*)d_in[13];
    float* out = (float*)d_out;

    float *p_xln, *p_x1, *p_xln2;
    cudaGetSymbolAddress((void**)&p_xln,  g_xln);
    cudaGetSymbolAddress((void**)&p_x1,   g_x1);
    cudaGetSymbolAddress((void**)&p_xln2, g_xln2);

    const int pass2_smem = (4 * 64 * P2_ROW + 128) * (int)sizeof(float);
    cudaFuncSetAttribute(attn_pass2, cudaFuncAttributeMaxDynamicSharedMemorySize, pass2_smem);

    zero_hard<<<1, 128>>>();
    ln_kernel<<<NTOK, 256>>>(x, g1, b1, p_xln);
    gemm_tf32<0><<<dim3(D_ / 64, NTOK / 128, 2), 256>>>(Wq, Wk);   // Q and K fused
    router_kernel<<<NTOK, 128>>>(Wr);
    vsel_kernel<<<NTOK, 384>>>(Wv);
    attn_pass1<<<dim3(S_ / 64, H_, B_), 256>>>();
    attn_pass2<<<dim3(S_ / 64, H_, B_), 256, pass2_smem>>>();
    osel_kernel<<<NTOK, 384>>>(Wo, x);
    ln_kernel<<<NTOK, 256>>>(p_x1, g2, b2, p_xln2);
    gate_kernel<<<NTOK, 256>>>(gff);
    capacity_kernel<<<1, 256>>>();
    gemm_tf32<1><<<dim3(DFF_ / 64, (CAP_ + 127) / 128, E_), 256>>>(W1, nullptr);
    gemm_tf32<2><<<dim3(D_ / 64, (CAP_ + 127) / 128, E_), 256>>>(W2, nullptr);
    combine_kernel<<<NTOK, 256>>>(out);
    if (out_size > NOUT) aux_kernel<<<1, 256>>>(out, out_size);
}

// round 8
// speedup vs baseline: 2.4517x; 1.1533x over previous
#include <cuda_runtime.h>
#include <math.h>

#define B_ 2
#define S_ 1024
#define D_ 768
#define H_ 12
#define E_ 8
#define DH_ 64
#define DFF_ 2048
#define NTOK (B_*S_)
#define CAP_ 320
#define NOUT (NTOK*D_)

// ---------------- scratch (device globals; no allocation allowed) -------------
__device__ float g_xln [NTOK*D_];
__device__ float g_q   [NTOK*D_];
__device__ float g_k   [NTOK*D_];
__device__ float g_vsel[NTOK*D_];
__device__ float g_attn[NTOK*D_];
__device__ float g_x1  [NTOK*D_];
__device__ float g_xln2[NTOK*D_];
__device__ float g_rlog[NTOK*(H_*E_)];
__device__ int   g_eidx[NTOK*H_];
__device__ int   g_hard[H_*E_];
__device__ float g_m[B_*H_*S_];
__device__ float g_l[B_*H_*S_];
__device__ int   g_tk_idx[NTOK*2];
__device__ float g_tk_prob[NTOK*2];
__device__ int   g_token_slot[NTOK*2];
__device__ int   g_slot_token[E_*CAP_];
__device__ float g_slot_w[E_*CAP_];
__device__ int   g_ecount[E_];
__device__ float g_hbuf[E_*CAP_*DFF_];
__device__ float g_sout[E_*CAP_*D_];

// ---------------- tf32 tensor-core helpers -------------------------------------
__device__ __forceinline__ unsigned to_tf32(float f) {
    unsigned u; asm("cvt.rna.tf32.f32 %0,%1;" : "=r"(u) : "f"(f)); return u;
}
__device__ __forceinline__ void mma_tf32(float c[4], const unsigned a[4], const unsigned b[2]) {
    asm("mma.sync.aligned.m16n8k8.row.col.f32.tf32.tf32.f32 "
        "{%0,%1,%2,%3},{%4,%5,%6,%7},{%8,%9},{%0,%1,%2,%3};"
        : "+f"(c[0]), "+f"(c[1]), "+f"(c[2]), "+f"(c[3])
        : "r"(a[0]), "r"(a[1]), "r"(a[2]), "r"(a[3]), "r"(b[0]), "r"(b[1]));
}

// ---------------- LayerNorm ---------------------------------------------------
__global__ void ln_kernel(const float* __restrict__ x, const float* __restrict__ g,
                          const float* __restrict__ b, float* __restrict__ out) {
    int row = blockIdx.x, tid = threadIdx.x;
    const float* xr = x + (size_t)row * D_;
    float s = 0.f, s2 = 0.f;
    for (int d = tid; d < D_; d += 256) { float v = xr[d]; s += v; s2 += v * v; }
    for (int o = 16; o > 0; o >>= 1) {
        s  += __shfl_down_sync(0xffffffffu, s,  o);
        s2 += __shfl_down_sync(0xffffffffu, s2, o);
    }
    __shared__ float sh[8], sh2[8];
    int w = tid >> 5, lane = tid & 31;
    if (lane == 0) { sh[w] = s; sh2[w] = s2; }
    __syncthreads();
    __shared__ float smean, sinv;
    if (tid == 0) {
        float a = 0.f, a2 = 0.f;
        for (int i = 0; i < 8; i++) { a += sh[i]; a2 += sh2[i]; }
        float mean = a / D_;
        float var  = a2 / D_ - mean * mean;
        smean = mean; sinv = rsqrtf(var + 1e-5f);
    }
    __syncthreads();
    float mean = smean, inv = sinv;
    for (int d = tid; d < D_; d += 256)
        out[(size_t)row * D_ + d] = (xr[d] - mean) * inv * g[d] + b[d];
}

// ---------------- tf32 tensor-core GEMM, 128x64x16 tiles -----------------------
#define ASTRIDE 20
#define BSTRIDE 72
template<int MODE>
__global__ __launch_bounds__(256)
void gemm_tf32(const float* __restrict__ P0, const float* __restrict__ P1) {
    __shared__ __align__(16) unsigned As[128 * ASTRIDE];
    __shared__ __align__(16) unsigned Bs[16 * BSTRIDE];

    const int tid = threadIdx.x, wid = tid >> 5, lane = tid & 31;
    const int e  = blockIdx.z;
    const int m0 = blockIdx.y * 128;
    const int n0 = blockIdx.x * 64;

    int N, K, count;
    const float* Bm;
    float* C;
    const float* Abase;
    if (MODE == 0) {
        N = D_; K = D_; count = NTOK;
        Bm = (e == 0) ? P0 : P1;
        C  = (e == 0) ? g_q : g_k;
        Abase = g_xln;
    } else if (MODE == 1) {
        N = DFF_; K = D_; count = g_ecount[e];
        if (count <= 0 || m0 >= count) return;
        Bm = P0 + (size_t)e * D_ * DFF_;
        C  = g_hbuf + (size_t)e * CAP_ * DFF_;
        Abase = g_xln2;
    } else {
        N = D_; K = DFF_; count = g_ecount[e];
        if (count <= 0 || m0 >= count) return;
        Bm = P0 + (size_t)e * DFF_ * D_;
        C  = g_sout + (size_t)e * CAP_ * D_;
        Abase = g_hbuf + (size_t)e * CAP_ * DFF_;
    }

    const int sm_r = tid >> 1;
    const int sm_k = (tid & 1) * 8;
    const int brow = tid >> 4;
    const int bcol = (tid & 15) * 4;

    const float* Aptr;
    {
        int r = m0 + sm_r;
        if (r >= count) r = count - 1;
        if (MODE == 1)
            Aptr = Abase + (size_t)g_slot_token[e * CAP_ + r] * D_ + sm_k;
        else
            Aptr = Abase + (size_t)r * K + sm_k;
    }
    const float* Bptr = Bm + (size_t)brow * N + n0 + bcol;

    const int wm0 = (wid & 3) * 32;
    const int wn0 = (wid >> 2) * 32;
    const int gr = lane >> 2, gc = lane & 3;

    float acc[2][4][4];
#pragma unroll
    for (int i = 0; i < 2; i++)
#pragma unroll
        for (int j = 0; j < 4; j++)
#pragma unroll
            for (int q = 0; q < 4; q++) acc[i][j][q] = 0.f;

    for (int k0 = 0; k0 < K; k0 += 16) {
        float4 av0 = *(const float4*)(Aptr + k0);
        float4 av1 = *(const float4*)(Aptr + k0 + 4);
        float4 bv  = *(const float4*)(Bptr + (size_t)k0 * N);
        uint4 u0 = make_uint4(to_tf32(av0.x), to_tf32(av0.y), to_tf32(av0.z), to_tf32(av0.w));
        uint4 u1 = make_uint4(to_tf32(av1.x), to_tf32(av1.y), to_tf32(av1.z), to_tf32(av1.w));
        uint4 ub = make_uint4(to_tf32(bv.x),  to_tf32(bv.y),  to_tf32(bv.z),  to_tf32(bv.w));
        *(uint4*)&As[sm_r * ASTRIDE + sm_k]     = u0;
        *(uint4*)&As[sm_r * ASTRIDE + sm_k + 4] = u1;
        *(uint4*)&Bs[brow * BSTRIDE + bcol]     = ub;
        __syncthreads();
#pragma unroll
        for (int kk = 0; kk < 16; kk += 8) {
            unsigned a[2][4];
#pragma unroll
            for (int mf = 0; mf < 2; mf++) {
                int mb = wm0 + mf * 16;
                a[mf][0] = As[(mb + gr)     * ASTRIDE + kk + gc];
                a[mf][1] = As[(mb + gr + 8) * ASTRIDE + kk + gc];
                a[mf][2] = As[(mb + gr)     * ASTRIDE + kk + gc + 4];
                a[mf][3] = As[(mb + gr + 8) * ASTRIDE + kk + gc + 4];
            }
#pragma unroll
            for (int nf = 0; nf < 4; nf++) {
                int nb = wn0 + nf * 8 + gr;
                unsigned b[2];
                b[0] = Bs[(kk + gc)     * BSTRIDE + nb];
                b[1] = Bs[(kk + gc + 4) * BSTRIDE + nb];
                mma_tf32(acc[0][nf], a[0], b);
                mma_tf32(acc[1][nf], a[1], b);
            }
        }
        __syncthreads();
    }

#pragma unroll
    for (int mf = 0; mf < 2; mf++) {
        int rbase = m0 + wm0 + mf * 16 + gr;
#pragma unroll
        for (int half = 0; half < 2; half++) {
            int r = rbase + half * 8;
            if (MODE != 0 && r >= count) continue;
            float w = 1.f;
            if (MODE == 2) w = g_slot_w[e * CAP_ + r];
#pragma unroll
            for (int nf = 0; nf < 4; nf++) {
                int cc = n0 + wn0 + nf * 8 + gc * 2;
                float v0 = acc[mf][nf][half * 2 + 0];
                float v1 = acc[mf][nf][half * 2 + 1];
                if (MODE == 1) { v0 = fmaxf(v0, 0.f); v1 = fmaxf(v1, 0.f); }
                else if (MODE == 2) { v0 *= w; v1 *= w; }
                *(float2*)(C + (size_t)r * N + cc) = make_float2(v0, v1);
            }
        }
    }
}

// ---------------- router as tf32 GEMM: logits = xln @ Wr  (M=NTOK,N=96,K=768) --
__global__ __launch_bounds__(256)
void router_gemm(const float* __restrict__ Wr) {
    __shared__ __align__(16) unsigned uA[64 * 36];
    __shared__ __align__(16) unsigned uB[32 * 100];
    const int tid = threadIdx.x, wid = tid >> 5, lane = tid & 31;
    const int gr = lane >> 2, gc = lane & 3;
    const int m0 = blockIdx.x * 64;
    const int wm0 = (wid & 3) * 16;
    const int wn0 = (wid >> 2) * 48;
    const int sr = tid & 63, sk = (tid >> 6) * 8;

    float acc[6][4];
#pragma unroll
    for (int i = 0; i < 6; i++)
#pragma unroll
        for (int q = 0; q < 4; q++) acc[i][q] = 0.f;

    for (int k0 = 0; k0 < D_; k0 += 32) {
        const float* asrc = g_xln + (size_t)(m0 + sr) * D_ + k0 + sk;
#pragma unroll
        for (int i = 0; i < 2; i++) {
            float4 v = *(const float4*)(asrc + i * 4);
            uA[sr * 36 + sk + i * 4 + 0] = to_tf32(v.x);
            uA[sr * 36 + sk + i * 4 + 1] = to_tf32(v.y);
            uA[sr * 36 + sk + i * 4 + 2] = to_tf32(v.z);
            uA[sr * 36 + sk + i * 4 + 3] = to_tf32(v.w);
        }
#pragma unroll
        for (int i = 0; i < 3; i++) {
            int v4 = tid + i * 256;           // 768 float4 loads of B tile
            int rw = v4 / 24, cl = (v4 % 24) * 4;
            float4 bv = *(const float4*)(Wr + (size_t)(k0 + rw) * 96 + cl);
            uB[rw * 100 + cl + 0] = to_tf32(bv.x);
            uB[rw * 100 + cl + 1] = to_tf32(bv.y);
            uB[rw * 100 + cl + 2] = to_tf32(bv.z);
            uB[rw * 100 + cl + 3] = to_tf32(bv.w);
        }
        __syncthreads();
#pragma unroll
        for (int kk = 0; kk < 32; kk += 8) {
            unsigned a[4];
            a[0] = uA[(wm0 + gr)     * 36 + kk + gc];
            a[1] = uA[(wm0 + gr + 8) * 36 + kk + gc];
            a[2] = uA[(wm0 + gr)     * 36 + kk + gc + 4];
            a[3] = uA[(wm0 + gr + 8) * 36 + kk + gc + 4];
#pragma unroll
            for (int nf = 0; nf < 6; nf++) {
                unsigned b[2];
                int nb = wn0 + nf * 8 + gr;
                b[0] = uB[(kk + gc)     * 100 + nb];
                b[1] = uB[(kk + gc + 4) * 100 + nb];
                mma_tf32(acc[nf], a, b);
            }
        }
        __syncthreads();
    }
#pragma unroll
    for (int nf = 0; nf < 6; nf++) {
        int col = wn0 + nf * 8 + 2 * gc;
        int row = m0 + wm0 + gr;
        *(float2*)&g_rlog[(size_t)row * 96 + col]       = make_float2(acc[nf][0], acc[nf][1]);
        *(float2*)&g_rlog[(size_t)(row + 8) * 96 + col] = make_float2(acc[nf][2], acc[nf][3]);
    }
}

__global__ void zero_hard() { int i = threadIdx.x; if (i < H_ * E_) g_hard[i] = 0; }

__global__ void router_argmax() {
    int idx = blockIdx.x * 256 + threadIdx.x;
    if (idx >= NTOK * H_) return;
    int row = idx / H_, h = idx - row * H_;
    const float* lg = g_rlog + (size_t)row * 96 + h * 8;
    float best = lg[0]; int bi = 0;
#pragma unroll
    for (int e = 1; e < E_; e++) { float v = lg[e]; if (v > best) { best = v; bi = e; } }
    g_eidx[row * H_ + h] = bi;
    atomicAdd(&g_hard[h * E_ + bi], 1);
}

// ---------------- per (token, head) expert matvecs ----------------------------
__global__ void vsel_kernel(const float* __restrict__ Wv) {
    int row = blockIdx.x, tid = threadIdx.x; // 384 = 12 warps
    int h = tid >> 5, lane = tid & 31;
    int e = g_eidx[row * H_ + h];
    const float* wv = Wv + (size_t)(h * E_ + e) * DH_ * DH_;
    const float* xh = g_xln + (size_t)row * D_ + h * DH_;
    float a0 = 0.f, a1 = 0.f, b0 = 0.f, b1 = 0.f;
    for (int d = 0; d < DH_; d += 2) {
        float x0 = xh[d], x1 = xh[d + 1];
        a0 += x0 * wv[d * DH_ + lane];
        b0 += x0 * wv[d * DH_ + lane + 32];
        a1 += x1 * wv[(d + 1) * DH_ + lane];
        b1 += x1 * wv[(d + 1) * DH_ + lane + 32];
    }
    g_vsel[(size_t)row * D_ + h * DH_ + lane]      = a0 + a1;
    g_vsel[(size_t)row * D_ + h * DH_ + lane + 32] = b0 + b1;
}

__global__ void osel_kernel(const float* __restrict__ Wo, const float* __restrict__ x) {
    int row = blockIdx.x, tid = threadIdx.x; // 384
    int h = tid >> 5, lane = tid & 31;
    int e = g_eidx[row * H_ + h];
    const float* wo = Wo + (size_t)(h * E_ + e) * DH_ * DH_;
    const float* af = g_attn + (size_t)row * D_ + h * DH_;
    float a0 = 0.f, a1 = 0.f, b0 = 0.f, b1 = 0.f;
    for (int f = 0; f < DH_; f += 2) {
        float v0 = af[f], v1 = af[f + 1];
        a0 += v0 * wo[f * DH_ + lane];
        b0 += v0 * wo[f * DH_ + lane + 32];
        a1 += v1 * wo[(f + 1) * DH_ + lane];
        b1 += v1 * wo[(f + 1) * DH_ + lane + 32];
    }
    size_t o0 = (size_t)row * D_ + h * DH_ + lane;
    g_x1[o0]      = x[o0]      + a0 + a1;
    g_x1[o0 + 32] = x[o0 + 32] + b0 + b1;
}

// ---------------- attention pass 1 (tf32 MMA): row stats m_s, l_s --------------
// smem: uQ [64][68] (A=[s][d]), uK [64][68] (B=[d][t]), Ss [64][72] scores
__global__ __launch_bounds__(256)
void attn_pass1() {
    extern __shared__ unsigned dsp[];
    unsigned* uQ = dsp;
    unsigned* uK = dsp + 64 * 68;
    float* Ss = (float*)(dsp + 2 * 64 * 68);
    int s0 = blockIdx.x * 64, h = blockIdx.y, b = blockIdx.z;
    int tid = threadIdx.x, wid = tid >> 5, lane = tid & 31;
    int gr = lane >> 2, gc = lane & 3;
    const float* qb = g_q + (size_t)b * S_ * D_ + h * DH_;
    const float* kb = g_k + (size_t)b * S_ * D_ + h * DH_;
    {
        int r = tid >> 2, dg = (tid & 3) * 16;
        const float* src = qb + (size_t)(s0 + r) * D_ + dg;
#pragma unroll
        for (int i = 0; i < 4; i++) {
            float4 v = *(const float4*)(src + i * 4);
            uQ[r * 68 + dg + i * 4 + 0] = to_tf32(v.x);
            uQ[r * 68 + dg + i * 4 + 1] = to_tf32(v.y);
            uQ[r * 68 + dg + i * 4 + 2] = to_tf32(v.z);
            uQ[r * 68 + dg + i * 4 + 3] = to_tf32(v.w);
        }
    }
    const int wm0 = (wid & 1) * 32, wn0 = (wid >> 1) * 16;
    const int rr = tid >> 2, qq = tid & 3;
    float run_m = -INFINITY, run_l = 0.f;

    for (int t0 = 0; t0 <= s0; t0 += 64) {
        {
            int r = tid >> 2, dg = (tid & 3) * 16;
            const float* src = kb + (size_t)(t0 + r) * D_ + dg;
#pragma unroll
            for (int i = 0; i < 4; i++) {
                float4 v = *(const float4*)(src + i * 4);
                uK[(dg + i * 4 + 0) * 68 + r] = to_tf32(v.x);
                uK[(dg + i * 4 + 1) * 68 + r] = to_tf32(v.y);
                uK[(dg + i * 4 + 2) * 68 + r] = to_tf32(v.z);
                uK[(dg + i * 4 + 3) * 68 + r] = to_tf32(v.w);
            }
        }
        __syncthreads();
        float c[2][2][4];
#pragma unroll
        for (int mf = 0; mf < 2; mf++)
#pragma unroll
            for (int nf = 0; nf < 2; nf++)
#pragma unroll
                for (int q = 0; q < 4; q++) c[mf][nf][q] = 0.f;
#pragma unroll
        for (int kk = 0; kk < 64; kk += 8) {
            unsigned a[2][4], bf[2][2];
#pragma unroll
            for (int mf = 0; mf < 2; mf++) {
                int mb = wm0 + mf * 16;
                a[mf][0] = uQ[(mb + gr)     * 68 + kk + gc];
                a[mf][1] = uQ[(mb + gr + 8) * 68 + kk + gc];
                a[mf][2] = uQ[(mb + gr)     * 68 + kk + gc + 4];
                a[mf][3] = uQ[(mb + gr + 8) * 68 + kk + gc + 4];
            }
#pragma unroll
            for (int nf = 0; nf < 2; nf++) {
                int nb = wn0 + nf * 8 + gr;
                bf[nf][0] = uK[(kk + gc)     * 68 + nb];
                bf[nf][1] = uK[(kk + gc + 4) * 68 + nb];
            }
#pragma unroll
            for (int mf = 0; mf < 2; mf++)
#pragma unroll
                for (int nf = 0; nf < 2; nf++)
                    mma_tf32(c[mf][nf], a[mf], bf[nf]);
        }
#pragma unroll
        for (int mf = 0; mf < 2; mf++)
#pragma unroll
            for (int nf = 0; nf < 2; nf++) {
                int row = wm0 + mf * 16 + gr, col = wn0 + nf * 8 + 2 * gc;
                *(float2*)&Ss[row * 72 + col]       = make_float2(c[mf][nf][0], c[mf][nf][1]);
                *(float2*)&Ss[(row + 8) * 72 + col] = make_float2(c[mf][nf][2], c[mf][nf][3]);
            }
        __syncthreads();
        // stats: 4 threads per row, 16 cols each
        float v[16];
#pragma unroll
        for (int i = 0; i < 4; i++) {
            float4 t4 = *(const float4*)&Ss[rr * 72 + qq * 16 + i * 4];
            v[i * 4 + 0] = t4.x; v[i * 4 + 1] = t4.y; v[i * 4 + 2] = t4.z; v[i * 4 + 3] = t4.w;
        }
        int gs = s0 + rr;
        float mx = -INFINITY;
#pragma unroll
        for (int cI = 0; cI < 16; cI++) {
            int gt = t0 + qq * 16 + cI;
            if (gt <= gs) mx = fmaxf(mx, v[cI] * 0.125f);
        }
        mx = fmaxf(mx, __shfl_xor_sync(0xffffffffu, mx, 1));
        mx = fmaxf(mx, __shfl_xor_sync(0xffffffffu, mx, 2));
        float mn = fmaxf(run_m, mx);
        float alpha = __expf(run_m - mn);
        float sum = 0.f;
#pragma unroll
        for (int cI = 0; cI < 16; cI++) {
            int gt = t0 + qq * 16 + cI;
            if (gt <= gs) sum += __expf(v[cI] * 0.125f - mn);
        }
        sum += __shfl_xor_sync(0xffffffffu, sum, 1);
        sum += __shfl_xor_sync(0xffffffffu, sum, 2);
        run_l = run_l * alpha + sum;
        run_m = mn;
    }
    if (qq == 0) {
        int o = (b * H_ + h) * S_ + s0 + rr;
        g_m[o] = run_m; g_l[o] = run_l;
    }
}

// ---------------- attention pass 2 (tf32 MMA): out[t] = sum_s P[s,t] v[s] ------
// smem: uK[64][68] B=[d][t]; uQ[64][68] A=[s][d]; uV[64][68] B=[s][f];
//       uP[64][72] A=Pt[t][s]; srm/sinv[64]
__global__ __launch_bounds__(256)
void attn_pass2() {
    extern __shared__ unsigned dsp2[];
    unsigned* uK = dsp2;
    unsigned* uQ = dsp2 + 4352;
    unsigned* uV = dsp2 + 8704;
    unsigned* uP = dsp2 + 13056;
    float* srm  = (float*)(dsp2 + 17664);
    float* sinv = srm + 64;
    int t0 = blockIdx.x * 64, h = blockIdx.y, b = blockIdx.z;
    int tid = threadIdx.x, wid = tid >> 5, lane = tid & 31;
    int gr = lane >> 2, gc = lane & 3;
    const float* qb = g_q    + (size_t)b * S_ * D_ + h * DH_;
    const float* kb = g_k    + (size_t)b * S_ * D_ + h * DH_;
    const float* vb = g_vsel + (size_t)b * S_ * D_ + h * DH_;
    {
        int r = tid >> 2, dg = (tid & 3) * 16;
        const float* src = kb + (size_t)(t0 + r) * D_ + dg;
#pragma unroll
        for (int i = 0; i < 4; i++) {
            float4 v = *(const float4*)(src + i * 4);
            uK[(dg + i * 4 + 0) * 68 + r] = to_tf32(v.x);
            uK[(dg + i * 4 + 1) * 68 + r] = to_tf32(v.y);
            uK[(dg + i * 4 + 2) * 68 + r] = to_tf32(v.z);
            uK[(dg + i * 4 + 3) * 68 + r] = to_tf32(v.w);
        }
    }
    const int wm0 = (wid & 1) * 32, wn0 = (wid >> 1) * 16;
    float O[2][2][4];
#pragma unroll
    for (int mf = 0; mf < 2; mf++)
#pragma unroll
        for (int nf = 0; nf < 2; nf++)
#pragma unroll
            for (int q = 0; q < 4; q++) O[mf][nf][q] = 0.f;

    for (int st0 = t0; st0 < S_; st0 += 64) {
        {
            int r = tid >> 2, dg = (tid & 3) * 16;
            const float* qsrc = qb + (size_t)(st0 + r) * D_ + dg;
            const float* vsrc = vb + (size_t)(st0 + r) * D_ + dg;
#pragma unroll
            for (int i = 0; i < 4; i++) {
                float4 v = *(const float4*)(qsrc + i * 4);
                uQ[r * 68 + dg + i * 4 + 0] = to_tf32(v.x);
                uQ[r * 68 + dg + i * 4 + 1] = to_tf32(v.y);
                uQ[r * 68 + dg + i * 4 + 2] = to_tf32(v.z);
                uQ[r * 68 + dg + i * 4 + 3] = to_tf32(v.w);
                float4 w = *(const float4*)(vsrc + i * 4);
                uV[r * 68 + dg + i * 4 + 0] = to_tf32(w.x);
                uV[r * 68 + dg + i * 4 + 1] = to_tf32(w.y);
                uV[r * 68 + dg + i * 4 + 2] = to_tf32(w.z);
                uV[r * 68 + dg + i * 4 + 3] = to_tf32(w.w);
            }
        }
        if (tid < 64) {
            int o = (b * H_ + h) * S_ + st0 + tid;
            srm[tid] = g_m[o]; sinv[tid] = 1.f / g_l[o];
        }
        __syncthreads();
        // scores: S[s][t]
        float c[2][2][4];
#pragma unroll
        for (int mf = 0; mf < 2; mf++)
#pragma unroll
            for (int nf = 0; nf < 2; nf++)
#pragma unroll
                for (int q = 0; q < 4; q++) c[mf][nf][q] = 0.f;
#pragma unroll
        for (int kk = 0; kk < 64; kk += 8) {
            unsigned a[2][4], bf[2][2];
#pragma unroll
            for (int mf = 0; mf < 2; mf++) {
                int mb = wm0 + mf * 16;
                a[mf][0] = uQ[(mb + gr)     * 68 + kk + gc];
                a[mf][1] = uQ[(mb + gr + 8) * 68 + kk + gc];
                a[mf][2] = uQ[(mb + gr)     * 68 + kk + gc + 4];
                a[mf][3] = uQ[(mb + gr + 8) * 68 + kk + gc + 4];
            }
#pragma unroll
            for (int nf = 0; nf < 2; nf++) {
                int nb = wn0 + nf * 8 + gr;
                bf[nf][0] = uK[(kk + gc)     * 68 + nb];
                bf[nf][1] = uK[(kk + gc + 4) * 68 + nb];
            }
#pragma unroll
            for (int mf = 0; mf < 2; mf++)
#pragma unroll
                for (int nf = 0; nf < 2; nf++)
                    mma_tf32(c[mf][nf], a[mf], bf[nf]);
        }
        // softmax-normalize, transpose into uP[t][s] (tf32)
#pragma unroll
        for (int mf = 0; mf < 2; mf++) {
            int sl_a = wm0 + mf * 16 + gr;
            int sl_b = sl_a + 8;
            int gs_a = st0 + sl_a, gs_b = st0 + sl_b;
            float ma = srm[sl_a], ia = sinv[sl_a];
            float mb2 = srm[sl_b], ib = sinv[sl_b];
#pragma unroll
            for (int nf = 0; nf < 2; nf++) {
                int tc = wn0 + nf * 8 + 2 * gc;
                int gt0 = t0 + tc, gt1 = gt0 + 1;
                float p;
                p = (gt0 <= gs_a) ? __expf(c[mf][nf][0] * 0.125f - ma) * ia : 0.f;
                uP[tc * 72 + sl_a] = to_tf32(p);
                p = (gt1 <= gs_a) ? __expf(c[mf][nf][1] * 0.125f - ma) * ia : 0.f;
                uP[(tc + 1) * 72 + sl_a] = to_tf32(p);
                p = (gt0 <= gs_b) ? __expf(c[mf][nf][2] * 0.125f - mb2) * ib : 0.f;
                uP[tc * 72 + sl_b] = to_tf32(p);
                p = (gt1 <= gs_b) ? __expf(c[mf][nf][3] * 0.125f - mb2) * ib : 0.f;
                uP[(tc + 1) * 72 + sl_b] = to_tf32(p);
            }
        }
        __syncthreads();
        // PV: O[t][f] += Pt[t][s] @ V[s][f]
#pragma unroll
        for (int kk = 0; kk < 64; kk += 8) {
            unsigned a[2][4], bf[2][2];
#pragma unroll
            for (int mf = 0; mf < 2; mf++) {
                int mb = wm0 + mf * 16;
                a[mf][0] = uP[(mb + gr)     * 72 + kk + gc];
                a[mf][1] = uP[(mb + gr + 8) * 72 + kk + gc];
                a[mf][2] = uP[(mb + gr)     * 72 + kk + gc + 4];
                a[mf][3] = uP[(mb + gr + 8) * 72 + kk + gc + 4];
            }
#pragma unroll
            for (int nf = 0; nf < 2; nf++) {
                int nb = wn0 + nf * 8 + gr;
                bf[nf][0] = uV[(kk + gc)     * 68 + nb];
                bf[nf][1] = uV[(kk + gc + 4) * 68 + nb];
            }
#pragma unroll
            for (int mf = 0; mf < 2; mf++)
#pragma unroll
                for (int nf = 0; nf < 2; nf++)
                    mma_tf32(O[mf][nf], a[mf], bf[nf]);
        }
        __syncthreads();
    }
#pragma unroll
    for (int mf = 0; mf < 2; mf++) {
        int trow = t0 + wm0 + mf * 16 + gr;
#pragma unroll
        for (int nf = 0; nf < 2; nf++) {
            int fc = wn0 + nf * 8 + 2 * gc;
            *(float2*)(g_attn + (size_t)(b * S_ + trow) * D_ + h * DH_ + fc)
                = make_float2(O[mf][nf][0], O[mf][nf][1]);
            *(float2*)(g_attn + (size_t)(b * S_ + trow + 8) * D_ + h * DH_ + fc)
                = make_float2(O[mf][nf][2], O[mf][nf][3]);
        }
    }
}

// ---------------- FFN gate + top-2 (warp per token) ----------------------------
__global__ void gate_kernel(const float* __restrict__ gff) {
    int wid = threadIdx.x >> 5, lane = threadIdx.x & 31;
    int row = blockIdx.x * 8 + wid;
    const float* xr = g_xln2 + (size_t)row * D_;
    float acc[8] = {};
    for (int d = lane; d < D_; d += 32) {
        float xv = xr[d];
        float4 gA = *(const float4*)(gff + (size_t)d * E_);
        float4 gB = *(const float4*)(gff + (size_t)d * E_ + 4);
        acc[0] += xv * gA.x; acc[1] += xv * gA.y; acc[2] += xv * gA.z; acc[3] += xv * gA.w;
        acc[4] += xv * gB.x; acc[5] += xv * gB.y; acc[6] += xv * gB.z; acc[7] += xv * gB.w;
    }
#pragma unroll
    for (int off = 16; off > 0; off >>= 1)
#pragma unroll
        for (int i = 0; i < 8; i++)
            acc[i] += __shfl_down_sync(0xffffffffu, acc[i], off);
    if (lane == 0) {
        int i0 = 0; float v0 = acc[0];
#pragma unroll
        for (int e = 1; e < E_; e++) if (acc[e] > v0) { v0 = acc[e]; i0 = e; }
        int i1 = -1; float v1 = -3.4e38f;
#pragma unroll
        for (int e = 0; e < E_; e++) { if (e == i0) continue; if (acc[e] > v1) { v1 = acc[e]; i1 = e; } }
        float e1 = expf(v1 - v0);
        float z = 1.f + e1;
        g_tk_idx[row * 2] = i0; g_tk_idx[row * 2 + 1] = i1;
        g_tk_prob[row * 2] = 1.f / z; g_tk_prob[row * 2 + 1] = e1 / z;
    }
}

// ---------------- capacity + deterministic slot assignment --------------------
__global__ void capacity_kernel() {
    int tid = threadIdx.x; // 256 = 8 warps, warp per expert
    int w = tid >> 5, lane = tid & 31;
    if (w < E_) {
        int e = w, c = 0;
        for (int i0 = 0; i0 < NTOK * 2; i0 += 32) {
            int i = i0 + lane;
            int idx = g_tk_idx[i];
            bool match = (idx == e);
            unsigned msk = __ballot_sync(0xffffffffu, match);
            if (match) {
                int rank = c + __popc(msk & ((1u << lane) - 1u));
                if (rank < CAP_) {
                    g_slot_token[e * CAP_ + rank] = i >> 1;
                    g_token_slot[i] = e * CAP_ + rank;
                } else {
                    g_token_slot[i] = -1;
                }
            }
            c += __popc(msk);
        }
        if (lane == 0) g_ecount[e] = (c < CAP_) ? c : CAP_;
    }
    __syncthreads();
    for (int t = tid; t < NTOK; t += 256) {
        int s0 = g_token_slot[2 * t], s1 = g_token_slot[2 * t + 1];
        float p0 = (s0 >= 0) ? g_tk_prob[2 * t]     : 0.f;
        float p1 = (s1 >= 0) ? g_tk_prob[2 * t + 1] : 0.f;
        float inv = 1.f / (p0 + p1 + 1e-9f);
        if (s0 >= 0) g_slot_w[s0] = p0 * inv;
        if (s1 >= 0) g_slot_w[s1] = p1 * inv;
    }
}

// ---------------- combine: out = x1 + f ----------------------------------------
__global__ void combine_kernel(float* __restrict__ out) {
    int row = blockIdx.x, tid = threadIdx.x;
    int s0 = g_token_slot[2 * row], s1 = g_token_slot[2 * row + 1];
    for (int d = tid; d < D_; d += 256) {
        float v = g_x1[(size_t)row * D_ + d];
        if (s0 >= 0) v += g_sout[(size_t)s0 * D_ + d];
        if (s1 >= 0) v += g_sout[(size_t)s1 * D_ + d];
        out[(size_t)row * D_ + d] = v;
    }
}

// ---------------- aux losses ---------------------------------------------------
__global__ void aux_kernel(float* __restrict__ out, int out_size) {
    __shared__ float sa;
    if (threadIdx.x == 0) {
        const float scale = 0.01f / 2048.f;
        float es = 0.f;
        for (int i = 0; i < H_ * E_; i++) es += g_hard[i] * scale;
        float a1 = 0.f;
        for (int i = 0; i < H_ * E_; i++) {
            float p = (g_hard[i] * scale) / (es + 1e-9f);
            a1 += p * p;
        }
        a1 *= (float)(E_ * H_);
        float tcs = 0.f, ics = 0.f, ic[E_];
        for (int e = 0; e < E_; e++) {
            float s = 0.f; int c = g_ecount[e];
            for (int r = 0; r < c; r++) s += g_slot_w[e * CAP_ + r];
            ic[e] = s; ics += s; tcs += (float)c;
        }
        float a2 = 0.f;
        for (int e = 0; e < E_; e++) a2 += ((float)g_ecount[e] / tcs) * (ic[e] / ics);
        a2 *= (float)E_;
        sa = a1 + a2;
    }
    __syncthreads();
    for (int i = NOUT + threadIdx.x; i < out_size; i += blockDim.x) out[i] = sa;
}

// ---------------- launch -------------------------------------------------------
extern "C" void kernel_launch(void* const* d_in, const int* in_sizes, int n_in,
                              void* d_out, int out_size) {
    const float* x   = (const float*)d_in[0];
    // d_in[1] = mask (pure causal 0/-1e9, applied analytically)
    const float* Wq  = (const float*)d_in[2];
    const float* Wk  = (const float*)d_in[3];
    const float* Wv  = (const float*)d_in[4];
    const float* Wo  = (const float*)d_in[5];
    const float* Wr  = (const float*)d_in[6];
    const float* g1  = (const float*)d_in[7];
    const float* b1  = (const float*)d_in[8];
    const float* g2  = (const float*)d_in[9];
    const float* b2  = (const float*)d_in[10];
    const float* gff = (const float*)d_in[11];
    const float* W1  = (const float*)d_in[12];
    const float* W2  = (const float*)d_in[13];
    float* out = (float*)d_out;

    float *p_xln, *p_x1, *p_xln2;
    cudaGetSymbolAddress((void**)&p_xln,  g_xln);
    cudaGetSymbolAddress((void**)&p_x1,   g_x1);
    cudaGetSymbolAddress((void**)&p_xln2, g_xln2);

    const int pass1_smem = (2 * 64 * 68 + 64 * 72) * 4;             // 53248 B
    const int pass2_smem = (3 * 64 * 68 + 64 * 72 + 128) * 4;       // 71168 B
    cudaFuncSetAttribute(attn_pass1, cudaFuncAttributeMaxDynamicSharedMemorySize, pass1_smem);
    cudaFuncSetAttribute(attn_pass2, cudaFuncAttributeMaxDynamicSharedMemorySize, pass2_smem);

    zero_hard<<<1, 128>>>();
    ln_kernel<<<NTOK, 256>>>(x, g1, b1, p_xln);
    gemm_tf32<0><<<dim3(D_ / 64, NTOK / 128, 2), 256>>>(Wq, Wk);   // Q and K fused
    router_gemm<<<NTOK / 64, 256>>>(Wr);
    router_argmax<<<(NTOK * H_ + 255) / 256, 256>>>();
    vsel_kernel<<<NTOK, 384>>>(Wv);
    attn_pass1<<<dim3(S_ / 64, H_, B_), 256, pass1_smem>>>();
    attn_pass2<<<dim3(S_ / 64, H_, B_), 256, pass2_smem>>>();
    osel_kernel<<<NTOK, 384>>>(Wo, x);
    ln_kernel<<<NTOK, 256>>>(p_x1, g2, b2, p_xln2);
    gate_kernel<<<NTOK / 8, 256>>>(gff);
    capacity_kernel<<<1, 256>>>();
    gemm_tf32<1><<<dim3(DFF_ / 64, (CAP_ + 127) / 128, E_), 256>>>(W1, nullptr);
    gemm_tf32<2><<<dim3(D_ / 64, (CAP_ + 127) / 128, E_), 256>>>(W2, nullptr);
    combine_kernel<<<NTOK, 256>>>(out);
    if (out_size > NOUT) aux_kernel<<<1, 256>>>(out, out_size);
}

// round 9
// speedup vs baseline: 2.8489x; 1.1620x over previous
#include <cuda_runtime.h>
#include <math.h>

#define B_ 2
#define S_ 1024
#define D_ 768
#define H_ 12
#define E_ 8
#define DH_ 64
#define DFF_ 2048
#define NTOK (B_*S_)
#define CAP_ 320
#define NOUT (NTOK*D_)

// ---------------- scratch (device globals; no allocation allowed) -------------
__device__ float g_xln [NTOK*D_];
__device__ float g_q   [NTOK*D_];
__device__ float g_k   [NTOK*D_];
__device__ float g_vsel[NTOK*D_];
__device__ float g_attn[NTOK*D_];
__device__ float g_x1  [NTOK*D_];
__device__ float g_xln2[NTOK*D_];
__device__ float g_rlog[NTOK*(H_*E_)];
__device__ int   g_eidx[NTOK*H_];
__device__ int   g_hard[H_*E_];
__device__ float g_m[B_*H_*S_];
__device__ float g_l[B_*H_*S_];
__device__ int   g_tk_idx[NTOK*2];
__device__ float g_tk_prob[NTOK*2];
__device__ int   g_token_slot[NTOK*2];
__device__ int   g_slot_token[E_*CAP_];
__device__ float g_slot_w[E_*CAP_];
__device__ int   g_ecount[E_];
__device__ float g_hbuf[E_*CAP_*DFF_];
__device__ float g_sout[E_*CAP_*D_];

// ---------------- tf32 tensor-core helpers -------------------------------------
__device__ __forceinline__ unsigned to_tf32(float f) {
    unsigned u; asm("cvt.rna.tf32.f32 %0,%1;" : "=r"(u) : "f"(f)); return u;
}
__device__ __forceinline__ void mma_tf32(float c[4], const unsigned a[4], const unsigned b[2]) {
    asm("mma.sync.aligned.m16n8k8.row.col.f32.tf32.tf32.f32 "
        "{%0,%1,%2,%3},{%4,%5,%6,%7},{%8,%9},{%0,%1,%2,%3};"
        : "+f"(c[0]), "+f"(c[1]), "+f"(c[2]), "+f"(c[3])
        : "r"(a[0]), "r"(a[1]), "r"(a[2]), "r"(a[3]), "r"(b[0]), "r"(b[1]));
}

// ---------------- LayerNorm (warp per row, float4) -----------------------------
__global__ void ln_kernel(const float* __restrict__ x, const float* __restrict__ g,
                          const float* __restrict__ b, float* __restrict__ out) {
    int wid = threadIdx.x >> 5, lane = threadIdx.x & 31;
    int row = blockIdx.x * 8 + wid;
    const float4* xr = (const float4*)(x + (size_t)row * D_);
    float4 v[6];
    float s = 0.f, s2 = 0.f;
#pragma unroll
    for (int i = 0; i < 6; i++) {
        v[i] = xr[lane + i * 32];
        s  += v[i].x + v[i].y + v[i].z + v[i].w;
        s2 += v[i].x * v[i].x + v[i].y * v[i].y + v[i].z * v[i].z + v[i].w * v[i].w;
    }
#pragma unroll
    for (int o = 16; o > 0; o >>= 1) {
        s  += __shfl_xor_sync(0xffffffffu, s,  o);
        s2 += __shfl_xor_sync(0xffffffffu, s2, o);
    }
    float mean = s * (1.f / D_);
    float inv  = rsqrtf(s2 * (1.f / D_) - mean * mean + 1e-5f);
    float4* orow = (float4*)(out + (size_t)row * D_);
    const float4* g4 = (const float4*)g;
    const float4* b4 = (const float4*)b;
#pragma unroll
    for (int i = 0; i < 6; i++) {
        float4 gg = g4[lane + i * 32], bb = b4[lane + i * 32];
        float4 o;
        o.x = (v[i].x - mean) * inv * gg.x + bb.x;
        o.y = (v[i].y - mean) * inv * gg.y + bb.y;
        o.z = (v[i].z - mean) * inv * gg.z + bb.z;
        o.w = (v[i].w - mean) * inv * gg.w + bb.w;
        orow[lane + i * 32] = o;
    }
}

// ---------------- tf32 tensor-core GEMM, 128x64x16 tiles -----------------------
// MODE 0: fused QKR. bx<12: Wq->g_q | bx<24: Wk->g_k | bx>=24: Wr->g_rlog (N=96)
// MODE 1: FFN GEMM1 (gathered A rows, ReLU). z=e. B=W1[e]. C=g_hbuf[e].
// MODE 2: FFN GEMM2 (slot-weight scale).     z=e. B=W2[e]. C=g_sout[e].
#define ASTRIDE 20
#define BSTRIDE 72
template<int MODE>
__global__ __launch_bounds__(256)
void gemm_tf32(const float* __restrict__ P0, const float* __restrict__ P1,
               const float* __restrict__ P2) {
    __shared__ __align__(16) unsigned As[128 * ASTRIDE];
    __shared__ __align__(16) unsigned Bs[16 * BSTRIDE];

    const int tid = threadIdx.x, wid = tid >> 5, lane = tid & 31;
    const int e  = blockIdx.z;
    const int m0 = blockIdx.y * 128;

    int N, K, count, n0;
    const float* Bm;
    float* C;
    const float* Abase;
    if (MODE == 0) {
        K = D_; count = NTOK; Abase = g_xln;
        int bx = blockIdx.x;
        if (bx < 12)      { Bm = P0; C = g_q;    N = D_; n0 = bx * 64; }
        else if (bx < 24) { Bm = P1; C = g_k;    N = D_; n0 = (bx - 12) * 64; }
        else              { Bm = P2; C = g_rlog; N = 96; n0 = (bx - 24) * 64; }
    } else if (MODE == 1) {
        N = DFF_; K = D_; count = g_ecount[e]; n0 = blockIdx.x * 64;
        if (count <= 0 || m0 >= count) return;
        Bm = P0 + (size_t)e * D_ * DFF_;
        C  = g_hbuf + (size_t)e * CAP_ * DFF_;
        Abase = g_xln2;
    } else {
        N = D_; K = DFF_; count = g_ecount[e]; n0 = blockIdx.x * 64;
        if (count <= 0 || m0 >= count) return;
        Bm = P0 + (size_t)e * DFF_ * D_;
        C  = g_sout + (size_t)e * CAP_ * D_;
        Abase = g_hbuf + (size_t)e * CAP_ * DFF_;
    }

    const int sm_r = tid >> 1;
    const int sm_k = (tid & 1) * 8;
    const int brow = tid >> 4;
    const int bcol = (tid & 15) * 4;

    const float* Aptr;
    {
        int r = m0 + sm_r;
        if (r >= count) r = count - 1;
        if (MODE == 1)
            Aptr = Abase + (size_t)g_slot_token[e * CAP_ + r] * D_ + sm_k;
        else
            Aptr = Abase + (size_t)r * K + sm_k;
    }
    // clamp B column so partial router tile stays in-bounds (garbage cols unused)
    int bc_eff = bcol;
    if (n0 + bcol + 4 > N) bc_eff = N - 4 - n0;
    const float* Bptr = Bm + (size_t)brow * N + n0 + bc_eff;

    const int wm0 = (wid & 3) * 32;
    const int wn0 = (wid >> 2) * 32;
    const int gr = lane >> 2, gc = lane & 3;

    float acc[2][4][4];
#pragma unroll
    for (int i = 0; i < 2; i++)
#pragma unroll
        for (int j = 0; j < 4; j++)
#pragma unroll
            for (int q = 0; q < 4; q++) acc[i][j][q] = 0.f;

    for (int k0 = 0; k0 < K; k0 += 16) {
        float4 av0 = *(const float4*)(Aptr + k0);
        float4 av1 = *(const float4*)(Aptr + k0 + 4);
        float4 bv  = *(const float4*)(Bptr + (size_t)k0 * N);
        uint4 u0 = make_uint4(to_tf32(av0.x), to_tf32(av0.y), to_tf32(av0.z), to_tf32(av0.w));
        uint4 u1 = make_uint4(to_tf32(av1.x), to_tf32(av1.y), to_tf32(av1.z), to_tf32(av1.w));
        uint4 ub = make_uint4(to_tf32(bv.x),  to_tf32(bv.y),  to_tf32(bv.z),  to_tf32(bv.w));
        *(uint4*)&As[sm_r * ASTRIDE + sm_k]     = u0;
        *(uint4*)&As[sm_r * ASTRIDE + sm_k + 4] = u1;
        *(uint4*)&Bs[brow * BSTRIDE + bcol]     = ub;
        __syncthreads();
#pragma unroll
        for (int kk = 0; kk < 16; kk += 8) {
            unsigned a[2][4];
#pragma unroll
            for (int mf = 0; mf < 2; mf++) {
                int mb = wm0 + mf * 16;
                a[mf][0] = As[(mb + gr)     * ASTRIDE + kk + gc];
                a[mf][1] = As[(mb + gr + 8) * ASTRIDE + kk + gc];
                a[mf][2] = As[(mb + gr)     * ASTRIDE + kk + gc + 4];
                a[mf][3] = As[(mb + gr + 8) * ASTRIDE + kk + gc + 4];
            }
#pragma unroll
            for (int nf = 0; nf < 4; nf++) {
                int nb = wn0 + nf * 8 + gr;
                unsigned b[2];
                b[0] = Bs[(kk + gc)     * BSTRIDE + nb];
                b[1] = Bs[(kk + gc + 4) * BSTRIDE + nb];
                mma_tf32(acc[0][nf], a[0], b);
                mma_tf32(acc[1][nf], a[1], b);
            }
        }
        __syncthreads();
    }

#pragma unroll
    for (int mf = 0; mf < 2; mf++) {
        int rbase = m0 + wm0 + mf * 16 + gr;
#pragma unroll
        for (int half = 0; half < 2; half++) {
            int r = rbase + half * 8;
            if (MODE != 0 && r >= count) continue;
            float w = 1.f;
            if (MODE == 2) w = g_slot_w[e * CAP_ + r];
#pragma unroll
            for (int nf = 0; nf < 4; nf++) {
                int cc = n0 + wn0 + nf * 8 + gc * 2;
                if (MODE == 0 && cc + 2 > N) continue;   // partial router tile
                float v0 = acc[mf][nf][half * 2 + 0];
                float v1 = acc[mf][nf][half * 2 + 1];
                if (MODE == 1) { v0 = fmaxf(v0, 0.f); v1 = fmaxf(v1, 0.f); }
                else if (MODE == 2) { v0 *= w; v1 *= w; }
                *(float2*)(C + (size_t)r * N + cc) = make_float2(v0, v1);
            }
        }
    }
}

__global__ void zero_hard() { int i = threadIdx.x; if (i < H_ * E_) g_hard[i] = 0; }

__global__ void router_argmax() {
    int idx = blockIdx.x * 256 + threadIdx.x;
    if (idx >= NTOK * H_) return;
    int row = idx / H_, h = idx - row * H_;
    const float* lg = g_rlog + (size_t)row * 96 + h * 8;
    float best = lg[0]; int bi = 0;
#pragma unroll
    for (int e = 1; e < E_; e++) { float v = lg[e]; if (v > best) { best = v; bi = e; } }
    g_eidx[row * H_ + h] = bi;
    atomicAdd(&g_hard[h * E_ + bi], 1);
}

// ---------------- per (token, head) expert matvecs ----------------------------
__global__ void vsel_kernel(const float* __restrict__ Wv) {
    int row = blockIdx.x, tid = threadIdx.x; // 384 = 12 warps
    int h = tid >> 5, lane = tid & 31;
    int e = g_eidx[row * H_ + h];
    const float* wv = Wv + (size_t)(h * E_ + e) * DH_ * DH_;
    const float* xh = g_xln + (size_t)row * D_ + h * DH_;
    float a0 = 0.f, a1 = 0.f, b0 = 0.f, b1 = 0.f;
#pragma unroll 8
    for (int d = 0; d < DH_; d += 2) {
        float x0 = xh[d], x1 = xh[d + 1];
        a0 += x0 * wv[d * DH_ + lane];
        b0 += x0 * wv[d * DH_ + lane + 32];
        a1 += x1 * wv[(d + 1) * DH_ + lane];
        b1 += x1 * wv[(d + 1) * DH_ + lane + 32];
    }
    g_vsel[(size_t)row * D_ + h * DH_ + lane]      = a0 + a1;
    g_vsel[(size_t)row * D_ + h * DH_ + lane + 32] = b0 + b1;
}

__global__ void osel_kernel(const float* __restrict__ Wo, const float* __restrict__ x) {
    int row = blockIdx.x, tid = threadIdx.x; // 384
    int h = tid >> 5, lane = tid & 31;
    int e = g_eidx[row * H_ + h];
    const float* wo = Wo + (size_t)(h * E_ + e) * DH_ * DH_;
    const float* af = g_attn + (size_t)row * D_ + h * DH_;
    float a0 = 0.f, a1 = 0.f, b0 = 0.f, b1 = 0.f;
#pragma unroll 8
    for (int f = 0; f < DH_; f += 2) {
        float v0 = af[f], v1 = af[f + 1];
        a0 += v0 * wo[f * DH_ + lane];
        b0 += v0 * wo[f * DH_ + lane + 32];
        a1 += v1 * wo[(f + 1) * DH_ + lane];
        b1 += v1 * wo[(f + 1) * DH_ + lane + 32];
    }
    size_t o0 = (size_t)row * D_ + h * DH_ + lane;
    g_x1[o0]      = x[o0]      + a0 + a1;
    g_x1[o0 + 32] = x[o0 + 32] + b0 + b1;
}

// ---------------- attention pass 1 (tf32 MMA): row stats m_s, l_s --------------
__global__ __launch_bounds__(256)
void attn_pass1() {
    extern __shared__ unsigned dsp[];
    unsigned* uQ = dsp;
    unsigned* uK = dsp + 64 * 68;
    float* Ss = (float*)(dsp + 2 * 64 * 68);
    int s0 = blockIdx.x * 64, h = blockIdx.y, b = blockIdx.z;
    int tid = threadIdx.x, wid = tid >> 5, lane = tid & 31;
    int gr = lane >> 2, gc = lane & 3;
    const float* qb = g_q + (size_t)b * S_ * D_ + h * DH_;
    const float* kb = g_k + (size_t)b * S_ * D_ + h * DH_;
    {
        int r = tid >> 2, dg = (tid & 3) * 16;
        const float* src = qb + (size_t)(s0 + r) * D_ + dg;
#pragma unroll
        for (int i = 0; i < 4; i++) {
            float4 v = *(const float4*)(src + i * 4);
            uQ[r * 68 + dg + i * 4 + 0] = to_tf32(v.x);
            uQ[r * 68 + dg + i * 4 + 1] = to_tf32(v.y);
            uQ[r * 68 + dg + i * 4 + 2] = to_tf32(v.z);
            uQ[r * 68 + dg + i * 4 + 3] = to_tf32(v.w);
        }
    }
    const int wm0 = (wid & 1) * 32, wn0 = (wid >> 1) * 16;
    const int rr = tid >> 2, qq = tid & 3;
    float run_m = -INFINITY, run_l = 0.f;

    for (int t0 = 0; t0 <= s0; t0 += 64) {
        {
            int r = tid >> 2, dg = (tid & 3) * 16;
            const float* src = kb + (size_t)(t0 + r) * D_ + dg;
#pragma unroll
            for (int i = 0; i < 4; i++) {
                float4 v = *(const float4*)(src + i * 4);
                uK[(dg + i * 4 + 0) * 68 + r] = to_tf32(v.x);
                uK[(dg + i * 4 + 1) * 68 + r] = to_tf32(v.y);
                uK[(dg + i * 4 + 2) * 68 + r] = to_tf32(v.z);
                uK[(dg + i * 4 + 3) * 68 + r] = to_tf32(v.w);
            }
        }
        __syncthreads();
        float c[2][2][4];
#pragma unroll
        for (int mf = 0; mf < 2; mf++)
#pragma unroll
            for (int nf = 0; nf < 2; nf++)
#pragma unroll
                for (int q = 0; q < 4; q++) c[mf][nf][q] = 0.f;
#pragma unroll
        for (int kk = 0; kk < 64; kk += 8) {
            unsigned a[2][4], bf[2][2];
#pragma unroll
            for (int mf = 0; mf < 2; mf++) {
                int mb = wm0 + mf * 16;
                a[mf][0] = uQ[(mb + gr)     * 68 + kk + gc];
                a[mf][1] = uQ[(mb + gr + 8) * 68 + kk + gc];
                a[mf][2] = uQ[(mb + gr)     * 68 + kk + gc + 4];
                a[mf][3] = uQ[(mb + gr + 8) * 68 + kk + gc + 4];
            }
#pragma unroll
            for (int nf = 0; nf < 2; nf++) {
                int nb = wn0 + nf * 8 + gr;
                bf[nf][0] = uK[(kk + gc)     * 68 + nb];
                bf[nf][1] = uK[(kk + gc + 4) * 68 + nb];
            }
#pragma unroll
            for (int mf = 0; mf < 2; mf++)
#pragma unroll
                for (int nf = 0; nf < 2; nf++)
                    mma_tf32(c[mf][nf], a[mf], bf[nf]);
        }
#pragma unroll
        for (int mf = 0; mf < 2; mf++)
#pragma unroll
            for (int nf = 0; nf < 2; nf++) {
                int row = wm0 + mf * 16 + gr, col = wn0 + nf * 8 + 2 * gc;
                *(float2*)&Ss[row * 72 + col]       = make_float2(c[mf][nf][0], c[mf][nf][1]);
                *(float2*)&Ss[(row + 8) * 72 + col] = make_float2(c[mf][nf][2], c[mf][nf][3]);
            }
        __syncthreads();
        float v[16];
#pragma unroll
        for (int i = 0; i < 4; i++) {
            float4 t4 = *(const float4*)&Ss[rr * 72 + qq * 16 + i * 4];
            v[i * 4 + 0] = t4.x; v[i * 4 + 1] = t4.y; v[i * 4 + 2] = t4.z; v[i * 4 + 3] = t4.w;
        }
        int gs = s0 + rr;
        float mx = -INFINITY;
#pragma unroll
        for (int cI = 0; cI < 16; cI++) {
            int gt = t0 + qq * 16 + cI;
            if (gt <= gs) mx = fmaxf(mx, v[cI] * 0.125f);
        }
        mx = fmaxf(mx, __shfl_xor_sync(0xffffffffu, mx, 1));
        mx = fmaxf(mx, __shfl_xor_sync(0xffffffffu, mx, 2));
        float mn = fmaxf(run_m, mx);
        float alpha = __expf(run_m - mn);
        float sum = 0.f;
#pragma unroll
        for (int cI = 0; cI < 16; cI++) {
            int gt = t0 + qq * 16 + cI;
            if (gt <= gs) sum += __expf(v[cI] * 0.125f - mn);
        }
        sum += __shfl_xor_sync(0xffffffffu, sum, 1);
        sum += __shfl_xor_sync(0xffffffffu, sum, 2);
        run_l = run_l * alpha + sum;
        run_m = mn;
    }
    if (qq == 0) {
        int o = (b * H_ + h) * S_ + s0 + rr;
        g_m[o] = run_m; g_l[o] = run_l;
    }
}

// ---------------- attention pass 2 (tf32 MMA): out[t] = sum_s P[s,t] v[s] ------
__global__ __launch_bounds__(256)
void attn_pass2() {
    extern __shared__ unsigned dsp2[];
    unsigned* uK = dsp2;
    unsigned* uQ = dsp2 + 4352;
    unsigned* uV = dsp2 + 8704;
    unsigned* uP = dsp2 + 13056;
    float* srm  = (float*)(dsp2 + 17664);
    float* sinv = srm + 64;
    int t0 = blockIdx.x * 64, h = blockIdx.y, b = blockIdx.z;
    int tid = threadIdx.x, wid = tid >> 5, lane = tid & 31;
    int gr = lane >> 2, gc = lane & 3;
    const float* qb = g_q    + (size_t)b * S_ * D_ + h * DH_;
    const float* kb = g_k    + (size_t)b * S_ * D_ + h * DH_;
    const float* vb = g_vsel + (size_t)b * S_ * D_ + h * DH_;
    {
        int r = tid >> 2, dg = (tid & 3) * 16;
        const float* src = kb + (size_t)(t0 + r) * D_ + dg;
#pragma unroll
        for (int i = 0; i < 4; i++) {
            float4 v = *(const float4*)(src + i * 4);
            uK[(dg + i * 4 + 0) * 68 + r] = to_tf32(v.x);
            uK[(dg + i * 4 + 1) * 68 + r] = to_tf32(v.y);
            uK[(dg + i * 4 + 2) * 68 + r] = to_tf32(v.z);
            uK[(dg + i * 4 + 3) * 68 + r] = to_tf32(v.w);
        }
    }
    const int wm0 = (wid & 1) * 32, wn0 = (wid >> 1) * 16;
    float O[2][2][4];
#pragma unroll
    for (int mf = 0; mf < 2; mf++)
#pragma unroll
        for (int nf = 0; nf < 2; nf++)
#pragma unroll
            for (int q = 0; q < 4; q++) O[mf][nf][q] = 0.f;

    for (int st0 = t0; st0 < S_; st0 += 64) {
        {
            int r = tid >> 2, dg = (tid & 3) * 16;
            const float* qsrc = qb + (size_t)(st0 + r) * D_ + dg;
            const float* vsrc = vb + (size_t)(st0 + r) * D_ + dg;
#pragma unroll
            for (int i = 0; i < 4; i++) {
                float4 v = *(const float4*)(qsrc + i * 4);
                uQ[r * 68 + dg + i * 4 + 0] = to_tf32(v.x);
                uQ[r * 68 + dg + i * 4 + 1] = to_tf32(v.y);
                uQ[r * 68 + dg + i * 4 + 2] = to_tf32(v.z);
                uQ[r * 68 + dg + i * 4 + 3] = to_tf32(v.w);
                float4 w = *(const float4*)(vsrc + i * 4);
                uV[r * 68 + dg + i * 4 + 0] = to_tf32(w.x);
                uV[r * 68 + dg + i * 4 + 1] = to_tf32(w.y);
                uV[r * 68 + dg + i * 4 + 2] = to_tf32(w.z);
                uV[r * 68 + dg + i * 4 + 3] = to_tf32(w.w);
            }
        }
        if (tid < 64) {
            int o = (b * H_ + h) * S_ + st0 + tid;
            srm[tid] = g_m[o]; sinv[tid] = 1.f / g_l[o];
        }
        __syncthreads();
        float c[2][2][4];
#pragma unroll
        for (int mf = 0; mf < 2; mf++)
#pragma unroll
            for (int nf = 0; nf < 2; nf++)
#pragma unroll
                for (int q = 0; q < 4; q++) c[mf][nf][q] = 0.f;
#pragma unroll
        for (int kk = 0; kk < 64; kk += 8) {
            unsigned a[2][4], bf[2][2];
#pragma unroll
            for (int mf = 0; mf < 2; mf++) {
                int mb = wm0 + mf * 16;
                a[mf][0] = uQ[(mb + gr)     * 68 + kk + gc];
                a[mf][1] = uQ[(mb + gr + 8) * 68 + kk + gc];
                a[mf][2] = uQ[(mb + gr)     * 68 + kk + gc + 4];
                a[mf][3] = uQ[(mb + gr + 8) * 68 + kk + gc + 4];
            }
#pragma unroll
            for (int nf = 0; nf < 2; nf++) {
                int nb = wn0 + nf * 8 + gr;
                bf[nf][0] = uK[(kk + gc)     * 68 + nb];
                bf[nf][1] = uK[(kk + gc + 4) * 68 + nb];
            }
#pragma unroll
            for (int mf = 0; mf < 2; mf++)
#pragma unroll
                for (int nf = 0; nf < 2; nf++)
                    mma_tf32(c[mf][nf], a[mf], bf[nf]);
        }
#pragma unroll
        for (int mf = 0; mf < 2; mf++) {
            int sl_a = wm0 + mf * 16 + gr;
            int sl_b = sl_a + 8;
            int gs_a = st0 + sl_a, gs_b = st0 + sl_b;
            float ma = srm[sl_a], ia = sinv[sl_a];
            float mb2 = srm[sl_b], ib = sinv[sl_b];
#pragma unroll
            for (int nf = 0; nf < 2; nf++) {
                int tc = wn0 + nf * 8 + 2 * gc;
                int gt0 = t0 + tc, gt1 = gt0 + 1;
                float p;
                p = (gt0 <= gs_a) ? __expf(c[mf][nf][0] * 0.125f - ma) * ia : 0.f;
                uP[tc * 72 + sl_a] = to_tf32(p);
                p = (gt1 <= gs_a) ? __expf(c[mf][nf][1] * 0.125f - ma) * ia : 0.f;
                uP[(tc + 1) * 72 + sl_a] = to_tf32(p);
                p = (gt0 <= gs_b) ? __expf(c[mf][nf][2] * 0.125f - mb2) * ib : 0.f;
                uP[tc * 72 + sl_b] = to_tf32(p);
                p = (gt1 <= gs_b) ? __expf(c[mf][nf][3] * 0.125f - mb2) * ib : 0.f;
                uP[(tc + 1) * 72 + sl_b] = to_tf32(p);
            }
        }
        __syncthreads();
#pragma unroll
        for (int kk = 0; kk < 64; kk += 8) {
            unsigned a[2][4], bf[2][2];
#pragma unroll
            for (int mf = 0; mf < 2; mf++) {
                int mb = wm0 + mf * 16;
                a[mf][0] = uP[(mb + gr)     * 72 + kk + gc];
                a[mf][1] = uP[(mb + gr + 8) * 72 + kk + gc];
                a[mf][2] = uP[(mb + gr)     * 72 + kk + gc + 4];
                a[mf][3] = uP[(mb + gr + 8) * 72 + kk + gc + 4];
            }
#pragma unroll
            for (int nf = 0; nf < 2; nf++) {
                int nb = wn0 + nf * 8 + gr;
                bf[nf][0] = uV[(kk + gc)     * 68 + nb];
                bf[nf][1] = uV[(kk + gc + 4) * 68 + nb];
            }
#pragma unroll
            for (int mf = 0; mf < 2; mf++)
#pragma unroll
                for (int nf = 0; nf < 2; nf++)
                    mma_tf32(O[mf][nf], a[mf], bf[nf]);
        }
        __syncthreads();
    }
#pragma unroll
    for (int mf = 0; mf < 2; mf++) {
        int trow = t0 + wm0 + mf * 16 + gr;
#pragma unroll
        for (int nf = 0; nf < 2; nf++) {
            int fc = wn0 + nf * 8 + 2 * gc;
            *(float2*)(g_attn + (size_t)(b * S_ + trow) * D_ + h * DH_ + fc)
                = make_float2(O[mf][nf][0], O[mf][nf][1]);
            *(float2*)(g_attn + (size_t)(b * S_ + trow + 8) * D_ + h * DH_ + fc)
                = make_float2(O[mf][nf][2], O[mf][nf][3]);
        }
    }
}

// ---------------- FFN gate + top-2 (warp per token) ----------------------------
__global__ void gate_kernel(const float* __restrict__ gff) {
    int wid = threadIdx.x >> 5, lane = threadIdx.x & 31;
    int row = blockIdx.x * 8 + wid;
    const float* xr = g_xln2 + (size_t)row * D_;
    float acc[8] = {};
    for (int d = lane; d < D_; d += 32) {
        float xv = xr[d];
        float4 gA = *(const float4*)(gff + (size_t)d * E_);
        float4 gB = *(const float4*)(gff + (size_t)d * E_ + 4);
        acc[0] += xv * gA.x; acc[1] += xv * gA.y; acc[2] += xv * gA.z; acc[3] += xv * gA.w;
        acc[4] += xv * gB.x; acc[5] += xv * gB.y; acc[6] += xv * gB.z; acc[7] += xv * gB.w;
    }
#pragma unroll
    for (int off = 16; off > 0; off >>= 1)
#pragma unroll
        for (int i = 0; i < 8; i++)
            acc[i] += __shfl_down_sync(0xffffffffu, acc[i], off);
    if (lane == 0) {
        int i0 = 0; float v0 = acc[0];
#pragma unroll
        for (int e = 1; e < E_; e++) if (acc[e] > v0) { v0 = acc[e]; i0 = e; }
        int i1 = -1; float v1 = -3.4e38f;
#pragma unroll
        for (int e = 0; e < E_; e++) { if (e == i0) continue; if (acc[e] > v1) { v1 = acc[e]; i1 = e; } }
        float e1 = expf(v1 - v0);
        float z = 1.f + e1;
        g_tk_idx[row * 2] = i0; g_tk_idx[row * 2 + 1] = i1;
        g_tk_prob[row * 2] = 1.f / z; g_tk_prob[row * 2 + 1] = e1 / z;
    }
}

// ---------------- capacity + deterministic slot assignment --------------------
__global__ void capacity_kernel() {
    int tid = threadIdx.x; // 256 = 8 warps, warp per expert
    int w = tid >> 5, lane = tid & 31;
    if (w < E_) {
        int e = w, c = 0;
        for (int i0 = 0; i0 < NTOK * 2; i0 += 32) {
            int i = i0 + lane;
            int idx = g_tk_idx[i];
            bool match = (idx == e);
            unsigned msk = __ballot_sync(0xffffffffu, match);
            if (match) {
                int rank = c + __popc(msk & ((1u << lane) - 1u));
                if (rank < CAP_) {
                    g_slot_token[e * CAP_ + rank] = i >> 1;
                    g_token_slot[i] = e * CAP_ + rank;
                } else {
                    g_token_slot[i] = -1;
                }
            }
            c += __popc(msk);
        }
        if (lane == 0) g_ecount[e] = (c < CAP_) ? c : CAP_;
    }
    __syncthreads();
    for (int t = tid; t < NTOK; t += 256) {
        int s0 = g_token_slot[2 * t], s1 = g_token_slot[2 * t + 1];
        float p0 = (s0 >= 0) ? g_tk_prob[2 * t]     : 0.f;
        float p1 = (s1 >= 0) ? g_tk_prob[2 * t + 1] : 0.f;
        float inv = 1.f / (p0 + p1 + 1e-9f);
        if (s0 >= 0) g_slot_w[s0] = p0 * inv;
        if (s1 >= 0) g_slot_w[s1] = p1 * inv;
    }
}

// ---------------- combine: out = x1 + f (warp per row, float4) -----------------
__global__ void combine_kernel(float* __restrict__ out) {
    int wid = threadIdx.x >> 5, lane = threadIdx.x & 31;
    int row = blockIdx.x * 8 + wid;
    int s0 = g_token_slot[2 * row], s1 = g_token_slot[2 * row + 1];
    const float4* xr = (const float4*)(g_x1 + (size_t)row * D_);
    const float4* f0 = (s0 >= 0) ? (const float4*)(g_sout + (size_t)s0 * D_) : nullptr;
    const float4* f1 = (s1 >= 0) ? (const float4*)(g_sout + (size_t)s1 * D_) : nullptr;
    float4* orow = (float4*)(out + (size_t)row * D_);
#pragma unroll
    for (int i = 0; i < 6; i++) {
        int c = lane + i * 32;
        float4 v = xr[c];
        if (f0) { float4 a = f0[c]; v.x += a.x; v.y += a.y; v.z += a.z; v.w += a.w; }
        if (f1) { float4 a = f1[c]; v.x += a.x; v.y += a.y; v.z += a.z; v.w += a.w; }
        orow[c] = v;
    }
}

// ---------------- aux losses (parallelized) ------------------------------------
__global__ void aux_kernel(float* __restrict__ out, int out_size) {
    __shared__ float ic_sh[E_];
    __shared__ float sa;
    int tid = threadIdx.x, w = tid >> 5, lane = tid & 31;
    if (w < E_) {
        int c = g_ecount[w];
        float s = 0.f;
        for (int r = lane; r < c; r += 32) s += g_slot_w[w * CAP_ + r];
#pragma unroll
        for (int o = 16; o > 0; o >>= 1) s += __shfl_down_sync(0xffffffffu, s, o);
        if (lane == 0) ic_sh[w] = s;
    }
    __syncthreads();
    if (tid == 0) {
        const float scale = 0.01f / 2048.f;
        float es = 0.f;
        for (int i = 0; i < H_ * E_; i++) es += g_hard[i] * scale;
        float a1 = 0.f;
        for (int i = 0; i < H_ * E_; i++) {
            float p = (g_hard[i] * scale) / (es + 1e-9f);
            a1 += p * p;
        }
        a1 *= (float)(E_ * H_);
        float tcs = 0.f, ics = 0.f;
        for (int e = 0; e < E_; e++) { tcs += (float)g_ecount[e]; ics += ic_sh[e]; }
        float a2 = 0.f;
        for (int e = 0; e < E_; e++) a2 += ((float)g_ecount[e] / tcs) * (ic_sh[e] / ics);
        a2 *= (float)E_;
        sa = a1 + a2;
    }
    __syncthreads();
    for (int i = NOUT + tid; i < out_size; i += blockDim.x) out[i] = sa;
}

// ---------------- launch -------------------------------------------------------
extern "C" void kernel_launch(void* const* d_in, const int* in_sizes, int n_in,
                              void* d_out, int out_size) {
    const float* x   = (const float*)d_in[0];
    // d_in[1] = mask (pure causal 0/-1e9, applied analytically)
    const float* Wq  = (const float*)d_in[2];
    const float* Wk  = (const float*)d_in[3];
    const float* Wv  = (const float*)d_in[4];
    const float* Wo  = (const float*)d_in[5];
    const float* Wr  = (const float*)d_in[6];
    const float* g1  = (const float*)d_in[7];
    const float* b1  = (const float*)d_in[8];
    const float* g2  = (const float*)d_in[9];
    const float* b2  = (const float*)d_in[10];
    const float* gff = (const float*)d_in[11];
    const float* W1  = (const float*)d_in[12];
    const float* W2  = (const float*)d_in[13];
    float* out = (float*)d_out;

    float *p_xln, *p_x1, *p_xln2;
    cudaGetSymbolAddress((void**)&p_xln,  g_xln);
    cudaGetSymbolAddress((void**)&p_x1,   g_x1);
    cudaGetSymbolAddress((void**)&p_xln2, g_xln2);

    const int pass1_smem = (2 * 64 * 68 + 64 * 72) * 4;
    const int pass2_smem = (3 * 64 * 68 + 64 * 72 + 128) * 4;
    cudaFuncSetAttribute(attn_pass1, cudaFuncAttributeMaxDynamicSharedMemorySize, pass1_smem);
    cudaFuncSetAttribute(attn_pass2, cudaFuncAttributeMaxDynamicSharedMemorySize, pass2_smem);

    zero_hard<<<1, 128>>>();
    ln_kernel<<<NTOK / 8, 256>>>(x, g1, b1, p_xln);
    gemm_tf32<0><<<dim3(26, NTOK / 128, 1), 256>>>(Wq, Wk, Wr);   // Q, K, router fused
    router_argmax<<<(NTOK * H_ + 255) / 256, 256>>>();
    vsel_kernel<<<NTOK, 384>>>(Wv);
    attn_pass1<<<dim3(S_ / 64, H_, B_), 256, pass1_smem>>>();
    attn_pass2<<<dim3(S_ / 64, H_, B_), 256, pass2_smem>>>();
    osel_kernel<<<NTOK, 384>>>(Wo, x);
    ln_kernel<<<NTOK / 8, 256>>>(p_x1, g2, b2, p_xln2);
    gate_kernel<<<NTOK / 8, 256>>>(gff);
    capacity_kernel<<<1, 256>>>();
    gemm_tf32<1><<<dim3(DFF_ / 64, (CAP_ + 127) / 128, E_), 256>>>(W1, nullptr, nullptr);
    gemm_tf32<2><<<dim3(D_ / 64, (CAP_ + 127) / 128, E_), 256>>>(W2, nullptr, nullptr);
    combine_kernel<<<NTOK / 8, 256>>>(out);
    if (out_size > NOUT) aux_kernel<<<1, 256>>>(out, out_size);
}